// round 12
// baseline (speedup 1.0000x reference)
#include <cuda_runtime.h>
#include <cuda_bf16.h>
#include <cstdint>

#define Bn 8
#define C_IN 128
#define C_OUT 128
#define K2 9
#define HH 64
#define WW 64
#define HW 4096
#define NOFF 18

// Scratch (no cudaMalloc allowed)
__device__ float g_xt[Bn * HW * C_IN];            // x NHWC fp32: [b][y][x][c]
__device__ __nv_bfloat16 g_xbh[Bn * HW * C_IN];   // x NHWC bf16 hi
__device__ __nv_bfloat16 g_xbl[Bn * HW * C_IN];   // x NHWC bf16 lo
// w_conv in mma B-fragment order: [tap][o16-group(8)][k16(8)][lane(32)][mat(4)]
__device__ uint32_t g_wfh[K2 * 8 * 8 * 32 * 4];   // hi pairs
__device__ uint32_t g_wfl[K2 * 8 * 8 * 32 * 4];   // lo pairs
// w_offset frags: [tap][ng(2)][k16(8)][lane(32)][mat(4)]
__device__ uint32_t g_wofh[K2 * 2 * 8 * 32 * 4];
__device__ uint32_t g_wofl[K2 * 2 * 8 * 32 * 4];

// ---------------------------------------------------------------------------
// Helpers (portable PTX: ldmatrix + mma.sync + cp.async, sm_80+)
// ---------------------------------------------------------------------------
__device__ __forceinline__ uint32_t smem_u32(const void* p) {
    uint32_t a;
    asm("{ .reg .u64 t; cvta.to.shared.u64 t, %1; cvt.u32.u64 %0, t; }"
        : "=r"(a) : "l"(p));
    return a;
}
__device__ __forceinline__ void ldsm_x4(uint32_t* r, uint32_t addr) {
    asm volatile("ldmatrix.sync.aligned.m8n8.x4.shared.b16 {%0,%1,%2,%3}, [%4];"
                 : "=r"(r[0]), "=r"(r[1]), "=r"(r[2]), "=r"(r[3]) : "r"(addr));
}
__device__ __forceinline__ void mma_bf16(float* c, const uint32_t* a,
                                         const uint32_t* b) {
    asm volatile(
        "mma.sync.aligned.m16n8k16.row.col.f32.bf16.bf16.f32 "
        "{%0,%1,%2,%3}, {%4,%5,%6,%7}, {%8,%9}, {%0,%1,%2,%3};"
        : "+f"(c[0]), "+f"(c[1]), "+f"(c[2]), "+f"(c[3])
        : "r"(a[0]), "r"(a[1]), "r"(a[2]), "r"(a[3]), "r"(b[0]), "r"(b[1]));
}
// hi = rn(v), lo = rn(v - float(hi)) for a pair (vx, vy); packed bf16x2.
__device__ __forceinline__ void split_pack(float vx, float vy,
                                           uint32_t& hp, uint32_t& lp) {
    asm("cvt.rn.bf16x2.f32 %0, %1, %2;" : "=r"(hp) : "f"(vy), "f"(vx));
    float hxf = __uint_as_float(hp << 16);
    float hyf = __uint_as_float(hp & 0xFFFF0000u);
    float rx = vx - hxf;
    float ry = vy - hyf;
    asm("cvt.rn.bf16x2.f32 %0, %1, %2;" : "=r"(lp) : "f"(ry), "f"(rx));
}
__device__ __forceinline__ void split_pack_s(float vx, float vy,
                                             uint32_t& hp, uint32_t& lp) {
    __nv_bfloat16 hx = __float2bfloat16_rn(vx);
    __nv_bfloat16 hy = __float2bfloat16_rn(vy);
    __nv_bfloat16 lx = __float2bfloat16_rn(vx - __bfloat162float(hx));
    __nv_bfloat16 ly = __float2bfloat16_rn(vy - __bfloat162float(hy));
    hp = (uint32_t)__bfloat16_as_ushort(hx)
       | ((uint32_t)__bfloat16_as_ushort(hy) << 16);
    lp = (uint32_t)__bfloat16_as_ushort(lx)
       | ((uint32_t)__bfloat16_as_ushort(ly) << 16);
}
__device__ __forceinline__ void cp_async16(uint32_t dst, const void* src,
                                           int srcsize) {
    asm volatile("cp.async.cg.shared.global [%0], [%1], 16, %2;"
                 :: "r"(dst), "l"(src), "r"(srcsize) : "memory");
}
#define CP_COMMIT() asm volatile("cp.async.commit_group;" ::: "memory")
#define CP_WAIT0()  asm volatile("cp.async.wait_group 0;" ::: "memory")

// ---------------------------------------------------------------------------
// NCHW -> NHWC transpose of x, fused with bf16 hi/lo split
// ---------------------------------------------------------------------------
__global__ void transpose_x_kernel(const float* __restrict__ x) {
    __shared__ float tile[32][33];
    int b = blockIdx.z;
    int hw0 = blockIdx.x * 32;
    int c0 = blockIdx.y * 32;
    const float* xb = x + (size_t)b * C_IN * HW;
    #pragma unroll
    for (int i = threadIdx.y; i < 32; i += 8)
        tile[i][threadIdx.x] = xb[(size_t)(c0 + i) * HW + hw0 + threadIdx.x];
    __syncthreads();
    size_t base = (size_t)b * HW * C_IN;
    #pragma unroll
    for (int i = threadIdx.y; i < 32; i += 8) {
        float v = tile[threadIdx.x][i];
        size_t idx = base + (size_t)(hw0 + i) * C_IN + c0 + threadIdx.x;
        g_xt[idx] = v;
        __nv_bfloat16 hi = __float2bfloat16_rn(v);
        g_xbh[idx] = hi;
        g_xbl[idx] = __float2bfloat16_rn(v - __bfloat162float(hi));
    }
}

// ---------------------------------------------------------------------------
// Weight prep: w_conv -> deform mma B-fragment order
// ---------------------------------------------------------------------------
__global__ void prep_wfrag_kernel(const float* __restrict__ wc) {
    int i = blockIdx.x * 256 + threadIdx.x;   // 0 .. 9*8*8*32-1
    if (i >= K2 * 8 * 8 * 32) return;
    int lane = i & 31;
    int kc = (i >> 5) & 7;
    int g = (i >> 8) & 7;
    int t = i >> 11;
    int ob = g * 16 + (lane >> 2);
    int kb = kc * 16 + (lane & 3) * 2;
    #pragma unroll
    for (int m = 0; m < 4; m++) {
        int o = ob + ((m >> 1) << 3);
        int k = kb + ((m & 1) << 3);
        float v0 = wc[(o * 128 + k) * 9 + t];
        float v1 = wc[(o * 128 + k + 1) * 9 + t];
        uint32_t hp, lp;
        split_pack_s(v0, v1, hp, lp);
        g_wfh[i * 4 + m] = hp;
        g_wfl[i * 4 + m] = lp;
    }
}

// ---------------------------------------------------------------------------
// Weight prep: w_offset -> mma B-fragment order [t][ng(2)][k16(8)][lane][4]
// ---------------------------------------------------------------------------
__global__ void prep_wofrag_kernel(const float* __restrict__ wo) {
    int i = blockIdx.x * 256 + threadIdx.x;   // 0 .. 9*2*8*32-1
    if (i >= K2 * 2 * 8 * 32) return;
    int lane = i & 31;
    int kc8 = (i >> 5) & 7;
    int ng = (i >> 8) & 1;
    int t = i >> 9;
    #pragma unroll
    for (int m = 0; m < 4; m++) {
        int o = ng * 16 + (lane >> 2) + ((m >> 1) << 3);
        int k = kc8 * 16 + (lane & 3) * 2 + ((m & 1) << 3);
        float v0 = (o < 18) ? wo[(o * 128 + k) * 9 + t] : 0.f;
        float v1 = (o < 18) ? wo[(o * 128 + k + 1) * 9 + t] : 0.f;
        uint32_t hp, lp;
        split_pack_s(v0, v1, hp, lp);
        g_wofh[i * 4 + m] = hp;
        g_wofl[i * 4 + m] = lp;
    }
}

// ---------------------------------------------------------------------------
// FUSED kernel. Per CTA (128 px x full image):
//   Phase 1: offset conv (cp.async im2col pipeline) -> offbuf in smem.
//   Phase 2: deformable conv, BRANCHLESS gather interleaved with MMA at
//            kc granularity (one straight-line block per kc step).
// SMEM (83232 B): A0[0,32K) A1[32K,64K) cw[64K,+4K) coff[68K,+4K)
//                 offbuf[72K, +9504)
// ---------------------------------------------------------------------------
#define DSM_A0 0u
#define DSM_A1 32768u
#define DSM_CW 65536u
#define DSM_CO 69632u
#define DSM_OFF 73728u
#define DSMEM_BYTES 83232

__global__ __launch_bounds__(256, 2) void fused_mma(float* __restrict__ out) {
    extern __shared__ char smem[];
    const uint32_t sb = smem_u32(smem);
    const int tid = threadIdx.x;
    const int lane = tid & 31;
    const int wid = tid >> 5;
    const int b = blockIdx.x >> 5;
    const int pix0 = (blockIdx.x & 31) * 128;

    float* offbuf = (float*)(smem + DSM_OFF);   // [ch][132]

    // ======================= Phase 1: offset conv =======================
    {
        float acc[4][4] = {};

        auto stage = [&](int hh) {
            int tap = hh >> 1;
            int c0 = (hh & 1) * 64;
            int ky = tap / 3 - 1, kx = tap % 3 - 1;
            uint32_t ab = sb + ((hh & 1) ? DSM_A1 : DSM_A0);
            #pragma unroll
            for (int q = 0; q < 8; q++) {
                int cid = tid + 256 * q;
                int p = cid >> 4, sub = cid & 15;
                int cc = sub & 7;
                int gp = pix0 + p;
                int y = (gp >> 6) + ky;
                int xx = (gp & 63) + kx;
                bool ok = ((unsigned)y < 64u) && ((unsigned)xx < 64u);
                const __nv_bfloat16* sp = (sub < 8 ? g_xbh : g_xbl)
                    + ((size_t)b * HW + (ok ? ((y << 6) + xx) : 0)) * 128
                    + c0 + cc * 8;
                uint32_t dst = ab + (uint32_t)p * 256u
                             + ((uint32_t)(cc ^ (p & 7)) << 4)
                             + (sub < 8 ? 0u : 128u);
                cp_async16(dst, sp, ok ? 16 : 0);
            }
        };

        stage(0);
        CP_COMMIT();

        for (int hh = 0; hh < 18; hh++) {
            CP_WAIT0();
            __syncthreads();
            if (hh + 1 < 18) { stage(hh + 1); CP_COMMIT(); }

            int tap = hh >> 1, half = hh & 1;
            uint32_t abu = sb + (half ? DSM_A1 : DSM_A0);
            #pragma unroll
            for (int kc = 0; kc < 4; kc++) {
                uint32_t ah[4], al[4];
                int mat = lane >> 3;
                int arow = wid * 16 + (lane & 7) + ((mat & 1) << 3);
                int kcol = kc * 16 + ((mat >> 1) << 3);
                uint32_t c = (uint32_t)(kcol >> 3);
                uint32_t aoff = (uint32_t)arow * 256u
                              + ((c ^ ((uint32_t)arow & 7u)) << 4);
                ldsm_x4(ah, abu + aoff);
                ldsm_x4(al, abu + aoff + 128);
                #pragma unroll
                for (int ng = 0; ng < 2; ng++) {
                    size_t fi = ((((size_t)tap * 2 + ng) * 8 + half * 4 + kc)
                                 * 32 + lane) * 4;
                    uint4 whf = *(const uint4*)(g_wofh + fi);
                    uint4 wlf = *(const uint4*)(g_wofl + fi);
                    uint32_t bh[4] = {whf.x, whf.y, whf.z, whf.w};
                    uint32_t bl[4] = {wlf.x, wlf.y, wlf.z, wlf.w};
                    mma_bf16(acc[ng * 2 + 0], ah, bh + 0);
                    mma_bf16(acc[ng * 2 + 1], ah, bh + 2);
                    mma_bf16(acc[ng * 2 + 0], al, bh + 0);
                    mma_bf16(acc[ng * 2 + 1], al, bh + 2);
                    mma_bf16(acc[ng * 2 + 0], ah, bl + 0);
                    mma_bf16(acc[ng * 2 + 1], ah, bl + 2);
                }
            }
        }
        __syncthreads();   // phase-1 MMAs done before offbuf writes race reads

        int pl = wid * 16 + (lane >> 2);
        #pragma unroll
        for (int nt = 0; nt < 4; nt++) {
            int ch = nt * 8 + (lane & 3) * 2;
            if (ch < 18) {
                offbuf[ch * 132 + pl]            = acc[nt][0];
                offbuf[(ch + 1) * 132 + pl]      = acc[nt][1];
                offbuf[ch * 132 + pl + 8]        = acc[nt][2];
                offbuf[(ch + 1) * 132 + pl + 8]  = acc[nt][3];
            }
        }
        __syncthreads();
    }

    // ======================= Phase 2: deformable conv ====================
    const int wy = wid & 3;          // px group: 32 px
    const int wx = wid >> 2;         // out group: 64 o

    float* cwbuf = (float*)(smem + DSM_CW);   // [par][j*128+p]
    int* cobuf = (int*)(smem + DSM_CO);
    const float* xb = g_xt + (size_t)b * HW * C_IN;

    float acc[2][8][4] = {};

    // per-tap bilinear setup: ALL 256 threads, 2 corners each (p = tid>>1)
    auto tap_setup = [&](int tap) {
        int p = tid >> 1;
        int par = tap & 1;
        int gp = pix0 + p;
        int h = gp >> 6, w = gp & 63;
        float dy = offbuf[(2 * tap) * 132 + p];
        float dx = offbuf[(2 * tap + 1) * 132 + p];
        float py = (float)(h - 1 + tap / 3) + dy;
        float px = (float)(w - 1 + tap % 3) + dx;
        float y0f = floorf(py), x0f = floorf(px);
        float fy = py - y0f, fx = px - x0f;
        int jbase = (tid & 1) * 2;
        #pragma unroll
        for (int jj = 0; jj < 2; jj++) {
            int j = jbase + jj;
            float yf = y0f + (float)(j >> 1);
            float xf = x0f + (float)(j & 1);
            bool ok = (yf >= 0.f && yf < 64.f && xf >= 0.f && xf < 64.f);
            float wy_ = (j >> 1) ? fy : 1.f - fy;
            float wx_ = (j & 1) ? fx : 1.f - fx;
            cwbuf[par * 512 + j * 128 + p] = ok ? wy_ * wx_ : 0.f;
            int yi = (int)fminf(fmaxf(yf, 0.f), 63.f);
            int xi = (int)fminf(fmaxf(xf, 0.f), 63.f);
            cobuf[par * 512 + j * 128 + p] = ((yi << 6) + xi) << 7;
        }
    };

    // branchless gather of 4 pixel-iterations for half hh2
    auto gather_quad = [&](int hh2, int i0) {
        int par = (hh2 >> 1) & 1;
        int c0 = (hh2 & 1) * 64;
        char* ab = smem + ((hh2 & 1) ? DSM_A1 : DSM_A0);
        const float* cw = cwbuf + par * 512;
        const int* co = cobuf + par * 512;
        #pragma unroll
        for (int i = i0; i < i0 + 4; i++) {
            int p = wid * 16 + i;
            float w0 = cw[p], w1 = cw[128 + p];
            float w2 = cw[256 + p], w3 = cw[384 + p];
            const float* base = xb + c0 + 2 * lane;
            float2 t0 = *(const float2*)(base + co[p]);
            float2 t1 = *(const float2*)(base + co[128 + p]);
            float2 t2 = *(const float2*)(base + co[256 + p]);
            float2 t3 = *(const float2*)(base + co[384 + p]);
            float vx = w0 * t0.x;
            float vy = w0 * t0.y;
            vx += w1 * t1.x;  vy += w1 * t1.y;
            vx += w2 * t2.x;  vy += w2 * t2.y;
            vx += w3 * t3.x;  vy += w3 * t3.y;
            uint32_t hp, lp;
            split_pack(vx, vy, hp, lp);
            uint32_t sw = (uint32_t)p * 256u
                        + ((((uint32_t)lane >> 2) ^ ((uint32_t)p & 7u)) << 4)
                        + (((uint32_t)lane & 3u) << 2);
            *(uint32_t*)(ab + sw) = hp;
            *(uint32_t*)(ab + sw + 128) = lp;
        }
    };

    tap_setup(0);
    __syncthreads();
    #pragma unroll
    for (int q = 0; q < 4; q++) gather_quad(0, q * 4);
    __syncthreads();

    for (int hh = 0; hh < 18; hh++) {
        int tap = hh >> 1;
        int half = hh & 1;

        if (half == 0 && tap + 1 < 9) tap_setup(tap + 1);

        // kc-interleaved: 4 gather iterations + 1 kc MMA block per step.
        // hh+1 == 18 gathers with stale (valid, clamped) coords into the
        // dead A0 buffer — harmless, keeps the body branchless.
        uint32_t abu = sb + (half ? DSM_A1 : DSM_A0);
        #pragma unroll
        for (int kc = 0; kc < 4; kc++) {
            gather_quad(hh + 1, kc * 4);

            uint32_t ah[2][4], al[2][4];
            #pragma unroll
            for (int mt = 0; mt < 2; mt++) {
                int mat = lane >> 3;
                int arow = wy * 32 + mt * 16 + (lane & 7) + ((mat & 1) << 3);
                int kcol = kc * 16 + ((mat >> 1) << 3);
                uint32_t c = (uint32_t)(kcol >> 3);
                uint32_t aoff = (uint32_t)arow * 256u
                              + ((c ^ ((uint32_t)arow & 7u)) << 4);
                ldsm_x4(ah[mt], abu + aoff);
                ldsm_x4(al[mt], abu + aoff + 128);
            }
            #pragma unroll
            for (int ng = 0; ng < 4; ng++) {
                int g = wx * 4 + ng;
                size_t fi = ((((size_t)tap * 8 + g) * 8 + half * 4 + kc) * 32
                             + lane) * 4;
                uint4 whf = *(const uint4*)(g_wfh + fi);
                uint4 wlf = *(const uint4*)(g_wfl + fi);
                uint32_t bh[4] = {whf.x, whf.y, whf.z, whf.w};
                uint32_t bl[4] = {wlf.x, wlf.y, wlf.z, wlf.w};
                #pragma unroll
                for (int mt = 0; mt < 2; mt++) {
                    mma_bf16(acc[mt][ng * 2 + 0], ah[mt], bh + 0);
                    mma_bf16(acc[mt][ng * 2 + 1], ah[mt], bh + 2);
                    mma_bf16(acc[mt][ng * 2 + 0], al[mt], bh + 0);
                    mma_bf16(acc[mt][ng * 2 + 1], al[mt], bh + 2);
                    mma_bf16(acc[mt][ng * 2 + 0], ah[mt], bl + 0);
                    mma_bf16(acc[mt][ng * 2 + 1], ah[mt], bl + 2);
                }
            }
        }
        __syncthreads();
    }

    // --- epilogue: c-frag -> out[b][o][px] ---
    float* ob = out + (size_t)b * 128 * HW;
    #pragma unroll
    for (int mt = 0; mt < 2; mt++) {
        int px0 = pix0 + wy * 32 + mt * 16 + (lane >> 2);
        #pragma unroll
        for (int nt = 0; nt < 8; nt++) {
            int o = wx * 64 + nt * 8 + (lane & 3) * 2;
            ob[(size_t)o * HW + px0]            = acc[mt][nt][0];
            ob[(size_t)(o + 1) * HW + px0]      = acc[mt][nt][1];
            ob[(size_t)o * HW + px0 + 8]        = acc[mt][nt][2];
            ob[(size_t)(o + 1) * HW + px0 + 8]  = acc[mt][nt][3];
        }
    }
}

// ---------------------------------------------------------------------------
extern "C" void kernel_launch(void* const* d_in, const int* in_sizes, int n_in,
                              void* d_out, int out_size) {
    const float* x  = (const float*)d_in[0];
    const float* wo = (const float*)d_in[1];   // w_offset
    const float* wc = (const float*)d_in[2];   // w_conv
    float* out = (float*)d_out;

    static bool attr_set = false;
    if (!attr_set) {
        cudaFuncSetAttribute(fused_mma,
                             cudaFuncAttributeMaxDynamicSharedMemorySize,
                             DSMEM_BYTES);
        attr_set = true;
    }

    dim3 tpb(32, 8);
    transpose_x_kernel<<<dim3(HW / 32, C_IN / 32, Bn), tpb>>>(x);
    prep_wfrag_kernel<<<(K2 * 8 * 8 * 32 + 255) / 256, 256>>>(wc);
    prep_wofrag_kernel<<<(K2 * 2 * 8 * 32 + 255) / 256, 256>>>(wo);
    fused_mma<<<Bn * (HW / 128), 256, DSMEM_BYTES>>>(out);
}

// round 13
// speedup vs baseline: 1.1166x; 1.1166x over previous
#include <cuda_runtime.h>
#include <cuda_bf16.h>
#include <cstdint>

#define Bn 8
#define C_IN 128
#define C_OUT 128
#define K2 9
#define HH 64
#define WW 64
#define HW 4096
#define NOFF 18

// Scratch (no cudaMalloc allowed)
__device__ float g_xt[Bn * HW * C_IN];            // x NHWC fp32: [b][y][x][c]
__device__ __nv_bfloat16 g_xbh[Bn * HW * C_IN];   // x NHWC bf16 hi
__device__ __nv_bfloat16 g_xbl[Bn * HW * C_IN];   // x NHWC bf16 lo
// w_conv in mma B-fragment order: [tap][o16-group(8)][k16(8)][lane(32)][mat(4)]
__device__ uint32_t g_wfh[K2 * 8 * 8 * 32 * 4];   // hi pairs
__device__ uint32_t g_wfl[K2 * 8 * 8 * 32 * 4];   // lo pairs
// w_offset frags: [tap][ng(2)][k16(8)][lane(32)][mat(4)]
__device__ uint32_t g_wofh[K2 * 2 * 8 * 32 * 4];
__device__ uint32_t g_wofl[K2 * 2 * 8 * 32 * 4];

// ---------------------------------------------------------------------------
// Helpers (portable PTX: ldmatrix + mma.sync + cp.async, sm_80+)
// ---------------------------------------------------------------------------
__device__ __forceinline__ uint32_t smem_u32(const void* p) {
    uint32_t a;
    asm("{ .reg .u64 t; cvta.to.shared.u64 t, %1; cvt.u32.u64 %0, t; }"
        : "=r"(a) : "l"(p));
    return a;
}
__device__ __forceinline__ void ldsm_x4(uint32_t* r, uint32_t addr) {
    asm volatile("ldmatrix.sync.aligned.m8n8.x4.shared.b16 {%0,%1,%2,%3}, [%4];"
                 : "=r"(r[0]), "=r"(r[1]), "=r"(r[2]), "=r"(r[3]) : "r"(addr));
}
__device__ __forceinline__ void mma_bf16(float* c, const uint32_t* a,
                                         const uint32_t* b) {
    asm volatile(
        "mma.sync.aligned.m16n8k16.row.col.f32.bf16.bf16.f32 "
        "{%0,%1,%2,%3}, {%4,%5,%6,%7}, {%8,%9}, {%0,%1,%2,%3};"
        : "+f"(c[0]), "+f"(c[1]), "+f"(c[2]), "+f"(c[3])
        : "r"(a[0]), "r"(a[1]), "r"(a[2]), "r"(a[3]), "r"(b[0]), "r"(b[1]));
}
// hi = rn(v), lo = rn(v - float(hi)) for a pair (vx, vy); packed bf16x2.
__device__ __forceinline__ void split_pack(float vx, float vy,
                                           uint32_t& hp, uint32_t& lp) {
    asm("cvt.rn.bf16x2.f32 %0, %1, %2;" : "=r"(hp) : "f"(vy), "f"(vx));
    float hxf = __uint_as_float(hp << 16);
    float hyf = __uint_as_float(hp & 0xFFFF0000u);
    float rx = vx - hxf;
    float ry = vy - hyf;
    asm("cvt.rn.bf16x2.f32 %0, %1, %2;" : "=r"(lp) : "f"(ry), "f"(rx));
}
__device__ __forceinline__ void split_pack_s(float vx, float vy,
                                             uint32_t& hp, uint32_t& lp) {
    __nv_bfloat16 hx = __float2bfloat16_rn(vx);
    __nv_bfloat16 hy = __float2bfloat16_rn(vy);
    __nv_bfloat16 lx = __float2bfloat16_rn(vx - __bfloat162float(hx));
    __nv_bfloat16 ly = __float2bfloat16_rn(vy - __bfloat162float(hy));
    hp = (uint32_t)__bfloat16_as_ushort(hx)
       | ((uint32_t)__bfloat16_as_ushort(hy) << 16);
    lp = (uint32_t)__bfloat16_as_ushort(lx)
       | ((uint32_t)__bfloat16_as_ushort(ly) << 16);
}
__device__ __forceinline__ void cp_async16(uint32_t dst, const void* src,
                                           int srcsize) {
    asm volatile("cp.async.cg.shared.global [%0], [%1], 16, %2;"
                 :: "r"(dst), "l"(src), "r"(srcsize) : "memory");
}
#define CP_COMMIT() asm volatile("cp.async.commit_group;" ::: "memory")
#define CP_WAIT0()  asm volatile("cp.async.wait_group 0;" ::: "memory")

// ---------------------------------------------------------------------------
// NCHW -> NHWC transpose of x, fused with bf16 hi/lo split
// ---------------------------------------------------------------------------
__global__ void transpose_x_kernel(const float* __restrict__ x) {
    __shared__ float tile[32][33];
    int b = blockIdx.z;
    int hw0 = blockIdx.x * 32;
    int c0 = blockIdx.y * 32;
    const float* xb = x + (size_t)b * C_IN * HW;
    #pragma unroll
    for (int i = threadIdx.y; i < 32; i += 8)
        tile[i][threadIdx.x] = xb[(size_t)(c0 + i) * HW + hw0 + threadIdx.x];
    __syncthreads();
    size_t base = (size_t)b * HW * C_IN;
    #pragma unroll
    for (int i = threadIdx.y; i < 32; i += 8) {
        float v = tile[threadIdx.x][i];
        size_t idx = base + (size_t)(hw0 + i) * C_IN + c0 + threadIdx.x;
        g_xt[idx] = v;
        __nv_bfloat16 hi = __float2bfloat16_rn(v);
        g_xbh[idx] = hi;
        g_xbl[idx] = __float2bfloat16_rn(v - __bfloat162float(hi));
    }
}

// ---------------------------------------------------------------------------
// Weight prep: w_conv -> deform mma B-fragment order
// ---------------------------------------------------------------------------
__global__ void prep_wfrag_kernel(const float* __restrict__ wc) {
    int i = blockIdx.x * 256 + threadIdx.x;   // 0 .. 9*8*8*32-1
    if (i >= K2 * 8 * 8 * 32) return;
    int lane = i & 31;
    int kc = (i >> 5) & 7;
    int g = (i >> 8) & 7;
    int t = i >> 11;
    int ob = g * 16 + (lane >> 2);
    int kb = kc * 16 + (lane & 3) * 2;
    #pragma unroll
    for (int m = 0; m < 4; m++) {
        int o = ob + ((m >> 1) << 3);
        int k = kb + ((m & 1) << 3);
        float v0 = wc[(o * 128 + k) * 9 + t];
        float v1 = wc[(o * 128 + k + 1) * 9 + t];
        uint32_t hp, lp;
        split_pack_s(v0, v1, hp, lp);
        g_wfh[i * 4 + m] = hp;
        g_wfl[i * 4 + m] = lp;
    }
}

// ---------------------------------------------------------------------------
// Weight prep: w_offset -> mma B-fragment order [t][ng(2)][k16(8)][lane][4]
// ---------------------------------------------------------------------------
__global__ void prep_wofrag_kernel(const float* __restrict__ wo) {
    int i = blockIdx.x * 256 + threadIdx.x;   // 0 .. 9*2*8*32-1
    if (i >= K2 * 2 * 8 * 32) return;
    int lane = i & 31;
    int kc8 = (i >> 5) & 7;
    int ng = (i >> 8) & 1;
    int t = i >> 9;
    #pragma unroll
    for (int m = 0; m < 4; m++) {
        int o = ng * 16 + (lane >> 2) + ((m >> 1) << 3);
        int k = kc8 * 16 + (lane & 3) * 2 + ((m & 1) << 3);
        float v0 = (o < 18) ? wo[(o * 128 + k) * 9 + t] : 0.f;
        float v1 = (o < 18) ? wo[(o * 128 + k + 1) * 9 + t] : 0.f;
        uint32_t hp, lp;
        split_pack_s(v0, v1, hp, lp);
        g_wofh[i * 4 + m] = hp;
        g_wofl[i * 4 + m] = lp;
    }
}

// ---------------------------------------------------------------------------
// FUSED kernel. Per CTA (128 px x full image):
//   Phase 1: offset conv (cp.async im2col pipeline, block-wide) -> offbuf.
//   Phase 2: deformable conv as 4 INDEPENDENT PAIR-PIPELINES:
//     pair wy = warps {wy, wy+4} (64 threads, named barrier wy+1):
//     owns px rows wy*32..wy*32+31, runs its own half-K double-buffered
//     gather->MMA pipeline. Pairs drift; no block-wide syncs in the loop.
// SMEM (83232 B): A0[0,32K) A1[32K,64K) cw[64K,+4K) coff[68K,+4K)
//                 offbuf[72K, +9504)
// ---------------------------------------------------------------------------
#define DSM_A0 0u
#define DSM_A1 32768u
#define DSM_CW 65536u
#define DSM_CO 69632u
#define DSM_OFF 73728u
#define DSMEM_BYTES 83232

__global__ __launch_bounds__(256, 2) void fused_mma(float* __restrict__ out) {
    extern __shared__ char smem[];
    const uint32_t sb = smem_u32(smem);
    const int tid = threadIdx.x;
    const int lane = tid & 31;
    const int wid = tid >> 5;
    const int b = blockIdx.x >> 5;
    const int pix0 = (blockIdx.x & 31) * 128;

    float* offbuf = (float*)(smem + DSM_OFF);   // [ch][132]

    // ======================= Phase 1: offset conv =======================
    {
        float acc[4][4] = {};

        auto stage = [&](int hh) {
            int tap = hh >> 1;
            int c0 = (hh & 1) * 64;
            int ky = tap / 3 - 1, kx = tap % 3 - 1;
            uint32_t ab = sb + ((hh & 1) ? DSM_A1 : DSM_A0);
            #pragma unroll
            for (int q = 0; q < 8; q++) {
                int cid = tid + 256 * q;
                int p = cid >> 4, sub = cid & 15;
                int cc = sub & 7;
                int gp = pix0 + p;
                int y = (gp >> 6) + ky;
                int xx = (gp & 63) + kx;
                bool ok = ((unsigned)y < 64u) && ((unsigned)xx < 64u);
                const __nv_bfloat16* sp = (sub < 8 ? g_xbh : g_xbl)
                    + ((size_t)b * HW + (ok ? ((y << 6) + xx) : 0)) * 128
                    + c0 + cc * 8;
                uint32_t dst = ab + (uint32_t)p * 256u
                             + ((uint32_t)(cc ^ (p & 7)) << 4)
                             + (sub < 8 ? 0u : 128u);
                cp_async16(dst, sp, ok ? 16 : 0);
            }
        };

        stage(0);
        CP_COMMIT();

        for (int hh = 0; hh < 18; hh++) {
            CP_WAIT0();
            __syncthreads();
            if (hh + 1 < 18) { stage(hh + 1); CP_COMMIT(); }

            int tap = hh >> 1, half = hh & 1;
            uint32_t abu = sb + (half ? DSM_A1 : DSM_A0);
            #pragma unroll
            for (int kc = 0; kc < 4; kc++) {
                uint32_t ah[4], al[4];
                int mat = lane >> 3;
                int arow = wid * 16 + (lane & 7) + ((mat & 1) << 3);
                int kcol = kc * 16 + ((mat >> 1) << 3);
                uint32_t c = (uint32_t)(kcol >> 3);
                uint32_t aoff = (uint32_t)arow * 256u
                              + ((c ^ ((uint32_t)arow & 7u)) << 4);
                ldsm_x4(ah, abu + aoff);
                ldsm_x4(al, abu + aoff + 128);
                #pragma unroll
                for (int ng = 0; ng < 2; ng++) {
                    size_t fi = ((((size_t)tap * 2 + ng) * 8 + half * 4 + kc)
                                 * 32 + lane) * 4;
                    uint4 whf = *(const uint4*)(g_wofh + fi);
                    uint4 wlf = *(const uint4*)(g_wofl + fi);
                    uint32_t bh[4] = {whf.x, whf.y, whf.z, whf.w};
                    uint32_t bl[4] = {wlf.x, wlf.y, wlf.z, wlf.w};
                    mma_bf16(acc[ng * 2 + 0], ah, bh + 0);
                    mma_bf16(acc[ng * 2 + 1], ah, bh + 2);
                    mma_bf16(acc[ng * 2 + 0], al, bh + 0);
                    mma_bf16(acc[ng * 2 + 1], al, bh + 2);
                    mma_bf16(acc[ng * 2 + 0], ah, bl + 0);
                    mma_bf16(acc[ng * 2 + 1], ah, bl + 2);
                }
            }
        }
        __syncthreads();   // phase-1 MMAs done before offbuf writes race reads

        int pl = wid * 16 + (lane >> 2);
        #pragma unroll
        for (int nt = 0; nt < 4; nt++) {
            int ch = nt * 8 + (lane & 3) * 2;
            if (ch < 18) {
                offbuf[ch * 132 + pl]            = acc[nt][0];
                offbuf[(ch + 1) * 132 + pl]      = acc[nt][1];
                offbuf[ch * 132 + pl + 8]        = acc[nt][2];
                offbuf[(ch + 1) * 132 + pl + 8]  = acc[nt][3];
            }
        }
        __syncthreads();
    }

    // ======================= Phase 2: deformable conv ====================
    const int wy = wid & 3;          // pair id: px rows wy*32..wy*32+31
    const int wx = wid >> 2;         // out group: 64 o
    const int pt = wx * 32 + lane;   // 0..63 thread index within pair

    float* cwbuf = (float*)(smem + DSM_CW);   // [par][j*128+p]
    int* cobuf = (int*)(smem + DSM_CO);
    const float* xb = g_xt + (size_t)b * HW * C_IN;

    float acc[2][8][4] = {};

    // pair-scope barrier (64 threads, named barrier wy+1)
    auto pair_sync = [&]() {
        asm volatile("bar.sync %0, 64;" :: "r"(wy + 1) : "memory");
    };

    // per-tap bilinear setup for the pair's own 32 px (2 corners/thread)
    auto tap_setup = [&](int tap) {
        int p = wy * 32 + (pt >> 1);
        int par = tap & 1;
        int gp = pix0 + p;
        int h = gp >> 6, w = gp & 63;
        float dy = offbuf[(2 * tap) * 132 + p];
        float dx = offbuf[(2 * tap + 1) * 132 + p];
        float py = (float)(h - 1 + tap / 3) + dy;
        float px = (float)(w - 1 + tap % 3) + dx;
        float y0f = floorf(py), x0f = floorf(px);
        float fy = py - y0f, fx = px - x0f;
        int jbase = (pt & 1) * 2;
        #pragma unroll
        for (int jj = 0; jj < 2; jj++) {
            int j = jbase + jj;
            float yf = y0f + (float)(j >> 1);
            float xf = x0f + (float)(j & 1);
            bool ok = (yf >= 0.f && yf < 64.f && xf >= 0.f && xf < 64.f);
            float wy_ = (j >> 1) ? fy : 1.f - fy;
            float wx_ = (j & 1) ? fx : 1.f - fx;
            cwbuf[par * 512 + j * 128 + p] = ok ? wy_ * wx_ : 0.f;
            int yi = (int)fminf(fmaxf(yf, 0.f), 63.f);
            int xi = (int)fminf(fmaxf(xf, 0.f), 63.f);
            cobuf[par * 512 + j * 128 + p] = ((yi << 6) + xi) << 7;
        }
    };

    // gather the pair's own 16 rows for half hh2 (branchy: skip zero weights)
    auto gather_half = [&](int hh2) {
        int par = (hh2 >> 1) & 1;
        int c0 = (hh2 & 1) * 64;
        char* ab = smem + ((hh2 & 1) ? DSM_A1 : DSM_A0);
        const float* cw = cwbuf + par * 512;
        const int* co = cobuf + par * 512;
        #pragma unroll 4
        for (int i = 0; i < 16; i++) {
            int p = wy * 32 + wx * 16 + i;
            float w0 = cw[p], w1 = cw[128 + p];
            float w2 = cw[256 + p], w3 = cw[384 + p];
            int o0 = co[p], o1 = co[128 + p];
            int o2 = co[256 + p], o3 = co[384 + p];
            float vx = 0.f, vy = 0.f;
            const float* base = xb + c0 + 2 * lane;
            if (w0 != 0.f) { float2 t = *(const float2*)(base + o0); vx += w0 * t.x; vy += w0 * t.y; }
            if (w1 != 0.f) { float2 t = *(const float2*)(base + o1); vx += w1 * t.x; vy += w1 * t.y; }
            if (w2 != 0.f) { float2 t = *(const float2*)(base + o2); vx += w2 * t.x; vy += w2 * t.y; }
            if (w3 != 0.f) { float2 t = *(const float2*)(base + o3); vx += w3 * t.x; vy += w3 * t.y; }
            uint32_t hp, lp;
            split_pack(vx, vy, hp, lp);
            uint32_t sw = (uint32_t)p * 256u
                        + ((((uint32_t)lane >> 2) ^ ((uint32_t)p & 7u)) << 4)
                        + (((uint32_t)lane & 3u) << 2);
            *(uint32_t*)(ab + sw) = hp;
            *(uint32_t*)(ab + sw + 128) = lp;
        }
    };

    tap_setup(0);
    pair_sync();
    gather_half(0);
    pair_sync();

    for (int hh = 0; hh < 18; hh++) {
        int tap = hh >> 1;
        int half = hh & 1;

        if (half == 0 && tap + 1 < 9) tap_setup(tap + 1);
        if (hh + 1 < 18) gather_half(hh + 1);

        uint32_t abu = sb + (half ? DSM_A1 : DSM_A0);
        #pragma unroll
        for (int kc = 0; kc < 4; kc++) {
            uint32_t ah[2][4], al[2][4];
            #pragma unroll
            for (int mt = 0; mt < 2; mt++) {
                int mat = lane >> 3;
                int arow = wy * 32 + mt * 16 + (lane & 7) + ((mat & 1) << 3);
                int kcol = kc * 16 + ((mat >> 1) << 3);
                uint32_t c = (uint32_t)(kcol >> 3);
                uint32_t aoff = (uint32_t)arow * 256u
                              + ((c ^ ((uint32_t)arow & 7u)) << 4);
                ldsm_x4(ah[mt], abu + aoff);
                ldsm_x4(al[mt], abu + aoff + 128);
            }
            #pragma unroll
            for (int ng = 0; ng < 4; ng++) {
                int g = wx * 4 + ng;
                size_t fi = ((((size_t)tap * 8 + g) * 8 + half * 4 + kc) * 32
                             + lane) * 4;
                uint4 whf = *(const uint4*)(g_wfh + fi);
                uint4 wlf = *(const uint4*)(g_wfl + fi);
                uint32_t bh[4] = {whf.x, whf.y, whf.z, whf.w};
                uint32_t bl[4] = {wlf.x, wlf.y, wlf.z, wlf.w};
                #pragma unroll
                for (int mt = 0; mt < 2; mt++) {
                    mma_bf16(acc[mt][ng * 2 + 0], ah[mt], bh + 0);
                    mma_bf16(acc[mt][ng * 2 + 1], ah[mt], bh + 2);
                    mma_bf16(acc[mt][ng * 2 + 0], al[mt], bh + 0);
                    mma_bf16(acc[mt][ng * 2 + 1], al[mt], bh + 2);
                    mma_bf16(acc[mt][ng * 2 + 0], ah[mt], bl + 0);
                    mma_bf16(acc[mt][ng * 2 + 1], ah[mt], bl + 2);
                }
            }
        }
        pair_sync();
    }

    // --- epilogue: c-frag -> out[b][o][px] ---
    float* ob = out + (size_t)b * 128 * HW;
    #pragma unroll
    for (int mt = 0; mt < 2; mt++) {
        int px0 = pix0 + wy * 32 + mt * 16 + (lane >> 2);
        #pragma unroll
        for (int nt = 0; nt < 8; nt++) {
            int o = wx * 64 + nt * 8 + (lane & 3) * 2;
            ob[(size_t)o * HW + px0]            = acc[mt][nt][0];
            ob[(size_t)(o + 1) * HW + px0]      = acc[mt][nt][1];
            ob[(size_t)o * HW + px0 + 8]        = acc[mt][nt][2];
            ob[(size_t)(o + 1) * HW + px0 + 8]  = acc[mt][nt][3];
        }
    }
}

// ---------------------------------------------------------------------------
extern "C" void kernel_launch(void* const* d_in, const int* in_sizes, int n_in,
                              void* d_out, int out_size) {
    const float* x  = (const float*)d_in[0];
    const float* wo = (const float*)d_in[1];   // w_offset
    const float* wc = (const float*)d_in[2];   // w_conv
    float* out = (float*)d_out;

    static bool attr_set = false;
    if (!attr_set) {
        cudaFuncSetAttribute(fused_mma,
                             cudaFuncAttributeMaxDynamicSharedMemorySize,
                             DSMEM_BYTES);
        attr_set = true;
    }

    dim3 tpb(32, 8);
    transpose_x_kernel<<<dim3(HW / 32, C_IN / 32, Bn), tpb>>>(x);
    prep_wfrag_kernel<<<(K2 * 8 * 8 * 32 + 255) / 256, 256>>>(wc);
    prep_wofrag_kernel<<<(K2 * 2 * 8 * 32 + 255) / 256, 256>>>(wo);
    fused_mma<<<Bn * (HW / 128), 256, DSMEM_BYTES>>>(out);
}

// round 14
// speedup vs baseline: 1.2720x; 1.1392x over previous
#include <cuda_runtime.h>
#include <cuda_bf16.h>
#include <cstdint>

#define Bn 8
#define C_IN 128
#define C_OUT 128
#define K2 9
#define HH 64
#define WW 64
#define HW 4096
#define NOFF 18

// Scratch (no cudaMalloc allowed)
__device__ float g_xt[Bn * HW * C_IN];            // x NHWC fp32: [b][y][x][c]
__device__ __nv_bfloat16 g_xbh[Bn * HW * C_IN];   // x NHWC bf16 hi
__device__ __nv_bfloat16 g_xbl[Bn * HW * C_IN];   // x NHWC bf16 lo
// w_conv in mma B-fragment order: [tap][o16-group(8)][k16(8)][lane(32)][mat(4)]
__device__ uint32_t g_wfh[K2 * 8 * 8 * 32 * 4];   // hi pairs
__device__ uint32_t g_wfl[K2 * 8 * 8 * 32 * 4];   // lo pairs
// w_offset frags: [tap][ng(2)][k16(8)][lane(32)][mat(4)]
__device__ uint32_t g_wofh[K2 * 2 * 8 * 32 * 4];
__device__ uint32_t g_wofl[K2 * 2 * 8 * 32 * 4];

// ---------------------------------------------------------------------------
// Helpers (portable PTX: ldmatrix + mma.sync + cp.async, sm_80+)
// ---------------------------------------------------------------------------
__device__ __forceinline__ uint32_t smem_u32(const void* p) {
    uint32_t a;
    asm("{ .reg .u64 t; cvta.to.shared.u64 t, %1; cvt.u32.u64 %0, t; }"
        : "=r"(a) : "l"(p));
    return a;
}
__device__ __forceinline__ void ldsm_x4(uint32_t* r, uint32_t addr) {
    asm volatile("ldmatrix.sync.aligned.m8n8.x4.shared.b16 {%0,%1,%2,%3}, [%4];"
                 : "=r"(r[0]), "=r"(r[1]), "=r"(r[2]), "=r"(r[3]) : "r"(addr));
}
__device__ __forceinline__ void mma_bf16(float* c, const uint32_t* a,
                                         const uint32_t* b) {
    asm volatile(
        "mma.sync.aligned.m16n8k16.row.col.f32.bf16.bf16.f32 "
        "{%0,%1,%2,%3}, {%4,%5,%6,%7}, {%8,%9}, {%0,%1,%2,%3};"
        : "+f"(c[0]), "+f"(c[1]), "+f"(c[2]), "+f"(c[3])
        : "r"(a[0]), "r"(a[1]), "r"(a[2]), "r"(a[3]), "r"(b[0]), "r"(b[1]));
}
// hi = rn(v), lo = rn(v - float(hi)) for a pair (vx, vy); packed bf16x2.
__device__ __forceinline__ void split_pack(float vx, float vy,
                                           uint32_t& hp, uint32_t& lp) {
    asm("cvt.rn.bf16x2.f32 %0, %1, %2;" : "=r"(hp) : "f"(vy), "f"(vx));
    float hxf = __uint_as_float(hp << 16);
    float hyf = __uint_as_float(hp & 0xFFFF0000u);
    float rx = vx - hxf;
    float ry = vy - hyf;
    asm("cvt.rn.bf16x2.f32 %0, %1, %2;" : "=r"(lp) : "f"(ry), "f"(rx));
}
__device__ __forceinline__ void split_pack_s(float vx, float vy,
                                             uint32_t& hp, uint32_t& lp) {
    __nv_bfloat16 hx = __float2bfloat16_rn(vx);
    __nv_bfloat16 hy = __float2bfloat16_rn(vy);
    __nv_bfloat16 lx = __float2bfloat16_rn(vx - __bfloat162float(hx));
    __nv_bfloat16 ly = __float2bfloat16_rn(vy - __bfloat162float(hy));
    hp = (uint32_t)__bfloat16_as_ushort(hx)
       | ((uint32_t)__bfloat16_as_ushort(hy) << 16);
    lp = (uint32_t)__bfloat16_as_ushort(lx)
       | ((uint32_t)__bfloat16_as_ushort(ly) << 16);
}
__device__ __forceinline__ void cp_async16(uint32_t dst, const void* src,
                                           int srcsize) {
    asm volatile("cp.async.cg.shared.global [%0], [%1], 16, %2;"
                 :: "r"(dst), "l"(src), "r"(srcsize) : "memory");
}
#define CP_COMMIT() asm volatile("cp.async.commit_group;" ::: "memory")
#define CP_WAIT0()  asm volatile("cp.async.wait_group 0;" ::: "memory")

// ---------------------------------------------------------------------------
// NCHW -> NHWC transpose of x, fused with bf16 hi/lo split
// ---------------------------------------------------------------------------
__global__ void transpose_x_kernel(const float* __restrict__ x) {
    __shared__ float tile[32][33];
    int b = blockIdx.z;
    int hw0 = blockIdx.x * 32;
    int c0 = blockIdx.y * 32;
    const float* xb = x + (size_t)b * C_IN * HW;
    #pragma unroll
    for (int i = threadIdx.y; i < 32; i += 8)
        tile[i][threadIdx.x] = xb[(size_t)(c0 + i) * HW + hw0 + threadIdx.x];
    __syncthreads();
    size_t base = (size_t)b * HW * C_IN;
    #pragma unroll
    for (int i = threadIdx.y; i < 32; i += 8) {
        float v = tile[threadIdx.x][i];
        size_t idx = base + (size_t)(hw0 + i) * C_IN + c0 + threadIdx.x;
        g_xt[idx] = v;
        __nv_bfloat16 hi = __float2bfloat16_rn(v);
        g_xbh[idx] = hi;
        g_xbl[idx] = __float2bfloat16_rn(v - __bfloat162float(hi));
    }
}

// ---------------------------------------------------------------------------
// Weight prep: w_conv -> deform mma B-fragment order
// ---------------------------------------------------------------------------
__global__ void prep_wfrag_kernel(const float* __restrict__ wc) {
    int i = blockIdx.x * 256 + threadIdx.x;   // 0 .. 9*8*8*32-1
    if (i >= K2 * 8 * 8 * 32) return;
    int lane = i & 31;
    int kc = (i >> 5) & 7;
    int g = (i >> 8) & 7;
    int t = i >> 11;
    int ob = g * 16 + (lane >> 2);
    int kb = kc * 16 + (lane & 3) * 2;
    #pragma unroll
    for (int m = 0; m < 4; m++) {
        int o = ob + ((m >> 1) << 3);
        int k = kb + ((m & 1) << 3);
        float v0 = wc[(o * 128 + k) * 9 + t];
        float v1 = wc[(o * 128 + k + 1) * 9 + t];
        uint32_t hp, lp;
        split_pack_s(v0, v1, hp, lp);
        g_wfh[i * 4 + m] = hp;
        g_wfl[i * 4 + m] = lp;
    }
}

// ---------------------------------------------------------------------------
// Weight prep: w_offset -> mma B-fragment order [t][ng(2)][k16(8)][lane][4]
// ---------------------------------------------------------------------------
__global__ void prep_wofrag_kernel(const float* __restrict__ wo) {
    int i = blockIdx.x * 256 + threadIdx.x;   // 0 .. 9*2*8*32-1
    if (i >= K2 * 2 * 8 * 32) return;
    int lane = i & 31;
    int kc8 = (i >> 5) & 7;
    int ng = (i >> 8) & 1;
    int t = i >> 9;
    #pragma unroll
    for (int m = 0; m < 4; m++) {
        int o = ng * 16 + (lane >> 2) + ((m >> 1) << 3);
        int k = kc8 * 16 + (lane & 3) * 2 + ((m & 1) << 3);
        float v0 = (o < 18) ? wo[(o * 128 + k) * 9 + t] : 0.f;
        float v1 = (o < 18) ? wo[(o * 128 + k + 1) * 9 + t] : 0.f;
        uint32_t hp, lp;
        split_pack_s(v0, v1, hp, lp);
        g_wofh[i * 4 + m] = hp;
        g_wofl[i * 4 + m] = lp;
    }
}

// ---------------------------------------------------------------------------
// FUSED kernel (R11 structure + float4 gather).
//   Phase 1: offset conv (cp.async im2col pipeline) -> offbuf in smem.
//   Phase 2: deformable conv, half-K double-buffered pipeline; gather uses
//            LDG.128 (4 cin/thread, warp = 2 px/iter, 8 iters per half).
// SMEM (83232 B): A0[0,32K) A1[32K,64K) cw[64K,+4K) coff[68K,+4K)
//                 offbuf[72K, +9504)
// ---------------------------------------------------------------------------
#define DSM_A0 0u
#define DSM_A1 32768u
#define DSM_CW 65536u
#define DSM_CO 69632u
#define DSM_OFF 73728u
#define DSMEM_BYTES 83232

__global__ __launch_bounds__(256, 2) void fused_mma(float* __restrict__ out) {
    extern __shared__ char smem[];
    const uint32_t sb = smem_u32(smem);
    const int tid = threadIdx.x;
    const int lane = tid & 31;
    const int wid = tid >> 5;
    const int b = blockIdx.x >> 5;
    const int pix0 = (blockIdx.x & 31) * 128;

    float* offbuf = (float*)(smem + DSM_OFF);   // [ch][132]

    // ======================= Phase 1: offset conv =======================
    {
        float acc[4][4] = {};

        auto stage = [&](int hh) {
            int tap = hh >> 1;
            int c0 = (hh & 1) * 64;
            int ky = tap / 3 - 1, kx = tap % 3 - 1;
            uint32_t ab = sb + ((hh & 1) ? DSM_A1 : DSM_A0);
            #pragma unroll
            for (int q = 0; q < 8; q++) {
                int cid = tid + 256 * q;
                int p = cid >> 4, sub = cid & 15;
                int cc = sub & 7;
                int gp = pix0 + p;
                int y = (gp >> 6) + ky;
                int xx = (gp & 63) + kx;
                bool ok = ((unsigned)y < 64u) && ((unsigned)xx < 64u);
                const __nv_bfloat16* sp = (sub < 8 ? g_xbh : g_xbl)
                    + ((size_t)b * HW + (ok ? ((y << 6) + xx) : 0)) * 128
                    + c0 + cc * 8;
                uint32_t dst = ab + (uint32_t)p * 256u
                             + ((uint32_t)(cc ^ (p & 7)) << 4)
                             + (sub < 8 ? 0u : 128u);
                cp_async16(dst, sp, ok ? 16 : 0);
            }
        };

        stage(0);
        CP_COMMIT();

        for (int hh = 0; hh < 18; hh++) {
            CP_WAIT0();
            __syncthreads();
            if (hh + 1 < 18) { stage(hh + 1); CP_COMMIT(); }

            int tap = hh >> 1, half = hh & 1;
            uint32_t abu = sb + (half ? DSM_A1 : DSM_A0);
            #pragma unroll
            for (int kc = 0; kc < 4; kc++) {
                uint32_t ah[4], al[4];
                int mat = lane >> 3;
                int arow = wid * 16 + (lane & 7) + ((mat & 1) << 3);
                int kcol = kc * 16 + ((mat >> 1) << 3);
                uint32_t c = (uint32_t)(kcol >> 3);
                uint32_t aoff = (uint32_t)arow * 256u
                              + ((c ^ ((uint32_t)arow & 7u)) << 4);
                ldsm_x4(ah, abu + aoff);
                ldsm_x4(al, abu + aoff + 128);
                #pragma unroll
                for (int ng = 0; ng < 2; ng++) {
                    size_t fi = ((((size_t)tap * 2 + ng) * 8 + half * 4 + kc)
                                 * 32 + lane) * 4;
                    uint4 whf = *(const uint4*)(g_wofh + fi);
                    uint4 wlf = *(const uint4*)(g_wofl + fi);
                    uint32_t bh[4] = {whf.x, whf.y, whf.z, whf.w};
                    uint32_t bl[4] = {wlf.x, wlf.y, wlf.z, wlf.w};
                    mma_bf16(acc[ng * 2 + 0], ah, bh + 0);
                    mma_bf16(acc[ng * 2 + 1], ah, bh + 2);
                    mma_bf16(acc[ng * 2 + 0], al, bh + 0);
                    mma_bf16(acc[ng * 2 + 1], al, bh + 2);
                    mma_bf16(acc[ng * 2 + 0], ah, bl + 0);
                    mma_bf16(acc[ng * 2 + 1], ah, bl + 2);
                }
            }
        }
        __syncthreads();   // phase-1 MMAs done before offbuf writes race reads

        int pl = wid * 16 + (lane >> 2);
        #pragma unroll
        for (int nt = 0; nt < 4; nt++) {
            int ch = nt * 8 + (lane & 3) * 2;
            if (ch < 18) {
                offbuf[ch * 132 + pl]            = acc[nt][0];
                offbuf[(ch + 1) * 132 + pl]      = acc[nt][1];
                offbuf[ch * 132 + pl + 8]        = acc[nt][2];
                offbuf[(ch + 1) * 132 + pl + 8]  = acc[nt][3];
            }
        }
        __syncthreads();
    }

    // ======================= Phase 2: deformable conv ====================
    const int wy = wid & 3;          // px group: 32 px
    const int wx = wid >> 2;         // out group: 64 o

    float* cwbuf = (float*)(smem + DSM_CW);   // [par][j*128+p]
    int* cobuf = (int*)(smem + DSM_CO);
    const float* xb = g_xt + (size_t)b * HW * C_IN;

    float acc[2][8][4] = {};

    // per-tap bilinear setup (128 threads, 1 px / 4 corners each)
    auto tap_setup = [&](int tap) {
        if (tid < 128) {
            int p = tid;
            int par = tap & 1;
            int gp = pix0 + p;
            int h = gp >> 6, w = gp & 63;
            float dy = offbuf[(2 * tap) * 132 + p];
            float dx = offbuf[(2 * tap + 1) * 132 + p];
            float py = (float)(h - 1 + tap / 3) + dy;
            float px = (float)(w - 1 + tap % 3) + dx;
            float y0f = floorf(py), x0f = floorf(px);
            float fy = py - y0f, fx = px - x0f;
            #pragma unroll
            for (int j = 0; j < 4; j++) {
                float yf = y0f + (float)(j >> 1);
                float xf = x0f + (float)(j & 1);
                bool ok = (yf >= 0.f && yf < 64.f && xf >= 0.f && xf < 64.f);
                float wy_ = (j >> 1) ? fy : 1.f - fy;
                float wx_ = (j & 1) ? fx : 1.f - fx;
                cwbuf[par * 512 + j * 128 + p] = ok ? wy_ * wx_ : 0.f;
                int yi = (int)fminf(fmaxf(yf, 0.f), 63.f);
                int xi = (int)fminf(fmaxf(xf, 0.f), 63.f);
                cobuf[par * 512 + j * 128 + p] = ((yi << 6) + xi) << 7;
            }
        }
    };

    // float4 gather: warp covers 2 px/iter (16 lanes x 4 cin each), 8 iters.
    auto gather_half = [&](int hh2) {
        int par = (hh2 >> 1) & 1;
        int c0 = (hh2 & 1) * 64;
        char* ab = smem + ((hh2 & 1) ? DSM_A1 : DSM_A0);
        const float* cw = cwbuf + par * 512;
        const int* co = cobuf + par * 512;
        int ln = lane & 15;
        int side = lane >> 4;
        const float* base = xb + c0 + 4 * ln;
        #pragma unroll 4
        for (int i = 0; i < 8; i++) {
            int p = wid * 16 + i * 2 + side;
            float w0 = cw[p], w1 = cw[128 + p];
            float w2 = cw[256 + p], w3 = cw[384 + p];
            int o0 = co[p], o1 = co[128 + p];
            int o2 = co[256 + p], o3 = co[384 + p];
            float v0 = 0.f, v1 = 0.f, v2 = 0.f, v3 = 0.f;
            if (w0 != 0.f) { float4 t = *(const float4*)(base + o0);
                v0 += w0 * t.x; v1 += w0 * t.y; v2 += w0 * t.z; v3 += w0 * t.w; }
            if (w1 != 0.f) { float4 t = *(const float4*)(base + o1);
                v0 += w1 * t.x; v1 += w1 * t.y; v2 += w1 * t.z; v3 += w1 * t.w; }
            if (w2 != 0.f) { float4 t = *(const float4*)(base + o2);
                v0 += w2 * t.x; v1 += w2 * t.y; v2 += w2 * t.z; v3 += w2 * t.w; }
            if (w3 != 0.f) { float4 t = *(const float4*)(base + o3);
                v0 += w3 * t.x; v1 += w3 * t.y; v2 += w3 * t.z; v3 += w3 * t.w; }
            uint32_t hp0, lp0, hp1, lp1;
            split_pack(v0, v1, hp0, lp0);
            split_pack(v2, v3, hp1, lp1);
            uint32_t chunk = (uint32_t)(ln >> 1);
            uint32_t sw = (uint32_t)p * 256u
                        + ((chunk ^ ((uint32_t)p & 7u)) << 4)
                        + ((uint32_t)(ln & 1) << 3);
            *(uint2*)(ab + sw) = make_uint2(hp0, hp1);
            *(uint2*)(ab + sw + 128) = make_uint2(lp0, lp1);
        }
    };

    tap_setup(0);
    __syncthreads();
    gather_half(0);
    __syncthreads();

    for (int hh = 0; hh < 18; hh++) {
        int tap = hh >> 1;
        int half = hh & 1;

        if (half == 0 && tap + 1 < 9) tap_setup(tap + 1);
        if (hh + 1 < 18) gather_half(hh + 1);

        uint32_t abu = sb + (half ? DSM_A1 : DSM_A0);
        #pragma unroll
        for (int kc = 0; kc < 4; kc++) {
            uint32_t ah[2][4], al[2][4];
            #pragma unroll
            for (int mt = 0; mt < 2; mt++) {
                int mat = lane >> 3;
                int arow = wy * 32 + mt * 16 + (lane & 7) + ((mat & 1) << 3);
                int kcol = kc * 16 + ((mat >> 1) << 3);
                uint32_t c = (uint32_t)(kcol >> 3);
                uint32_t aoff = (uint32_t)arow * 256u
                              + ((c ^ ((uint32_t)arow & 7u)) << 4);
                ldsm_x4(ah[mt], abu + aoff);
                ldsm_x4(al[mt], abu + aoff + 128);
            }
            #pragma unroll
            for (int ng = 0; ng < 4; ng++) {
                int g = wx * 4 + ng;
                size_t fi = ((((size_t)tap * 8 + g) * 8 + half * 4 + kc) * 32
                             + lane) * 4;
                uint4 whf = *(const uint4*)(g_wfh + fi);
                uint4 wlf = *(const uint4*)(g_wfl + fi);
                uint32_t bh[4] = {whf.x, whf.y, whf.z, whf.w};
                uint32_t bl[4] = {wlf.x, wlf.y, wlf.z, wlf.w};
                #pragma unroll
                for (int mt = 0; mt < 2; mt++) {
                    mma_bf16(acc[mt][ng * 2 + 0], ah[mt], bh + 0);
                    mma_bf16(acc[mt][ng * 2 + 1], ah[mt], bh + 2);
                    mma_bf16(acc[mt][ng * 2 + 0], al[mt], bh + 0);
                    mma_bf16(acc[mt][ng * 2 + 1], al[mt], bh + 2);
                    mma_bf16(acc[mt][ng * 2 + 0], ah[mt], bl + 0);
                    mma_bf16(acc[mt][ng * 2 + 1], ah[mt], bl + 2);
                }
            }
        }
        __syncthreads();
    }

    // --- epilogue: c-frag -> out[b][o][px] ---
    float* ob = out + (size_t)b * 128 * HW;
    #pragma unroll
    for (int mt = 0; mt < 2; mt++) {
        int px0 = pix0 + wy * 32 + mt * 16 + (lane >> 2);
        #pragma unroll
        for (int nt = 0; nt < 8; nt++) {
            int o = wx * 64 + nt * 8 + (lane & 3) * 2;
            ob[(size_t)o * HW + px0]            = acc[mt][nt][0];
            ob[(size_t)(o + 1) * HW + px0]      = acc[mt][nt][1];
            ob[(size_t)o * HW + px0 + 8]        = acc[mt][nt][2];
            ob[(size_t)(o + 1) * HW + px0 + 8]  = acc[mt][nt][3];
        }
    }
}

// ---------------------------------------------------------------------------
extern "C" void kernel_launch(void* const* d_in, const int* in_sizes, int n_in,
                              void* d_out, int out_size) {
    const float* x  = (const float*)d_in[0];
    const float* wo = (const float*)d_in[1];   // w_offset
    const float* wc = (const float*)d_in[2];   // w_conv
    float* out = (float*)d_out;

    static bool attr_set = false;
    if (!attr_set) {
        cudaFuncSetAttribute(fused_mma,
                             cudaFuncAttributeMaxDynamicSharedMemorySize,
                             DSMEM_BYTES);
        attr_set = true;
    }

    dim3 tpb(32, 8);
    transpose_x_kernel<<<dim3(HW / 32, C_IN / 32, Bn), tpb>>>(x);
    prep_wfrag_kernel<<<(K2 * 8 * 8 * 32 + 255) / 256, 256>>>(wc);
    prep_wofrag_kernel<<<(K2 * 2 * 8 * 32 + 255) / 256, 256>>>(wo);
    fused_mma<<<Bn * (HW / 128), 256, DSMEM_BYTES>>>(out);
}

// round 15
// speedup vs baseline: 1.4569x; 1.1454x over previous
#include <cuda_runtime.h>
#include <cuda_fp16.h>
#include <cstdint>

#define Bn 8
#define C_IN 128
#define C_OUT 128
#define K2 9
#define HH 64
#define WW 64
#define HW 4096
#define NOFF 18

// Scratch (no cudaMalloc allowed)
__device__ float g_xt[Bn * HW * C_IN];            // x NHWC fp32: [b][y][x][c]
__device__ __half g_xbh[Bn * HW * C_IN];          // x NHWC fp16 hi
__device__ __half g_xbl[Bn * HW * C_IN];          // x NHWC fp16 lo
// w_conv in mma B-fragment order: [tap][o16-group(8)][k16(8)][lane(32)][mat(4)]
// single fp16 per weight (11-bit mantissa, rel err ~2^-12)
__device__ uint32_t g_wfh[K2 * 8 * 8 * 32 * 4];
// w_offset frags (fp16 hi/lo, 3-term): [tap][ng(2)][k16(8)][lane(32)][mat(4)]
__device__ uint32_t g_wofh[K2 * 2 * 8 * 32 * 4];
__device__ uint32_t g_wofl[K2 * 2 * 8 * 32 * 4];

// ---------------------------------------------------------------------------
// Helpers (portable PTX: ldmatrix + mma.sync + cp.async, sm_80+)
// ---------------------------------------------------------------------------
__device__ __forceinline__ uint32_t smem_u32(const void* p) {
    uint32_t a;
    asm("{ .reg .u64 t; cvta.to.shared.u64 t, %1; cvt.u32.u64 %0, t; }"
        : "=r"(a) : "l"(p));
    return a;
}
__device__ __forceinline__ void ldsm_x4(uint32_t* r, uint32_t addr) {
    asm volatile("ldmatrix.sync.aligned.m8n8.x4.shared.b16 {%0,%1,%2,%3}, [%4];"
                 : "=r"(r[0]), "=r"(r[1]), "=r"(r[2]), "=r"(r[3]) : "r"(addr));
}
__device__ __forceinline__ void mma_f16(float* c, const uint32_t* a,
                                        const uint32_t* b) {
    asm volatile(
        "mma.sync.aligned.m16n8k16.row.col.f32.f16.f16.f32 "
        "{%0,%1,%2,%3}, {%4,%5,%6,%7}, {%8,%9}, {%0,%1,%2,%3};"
        : "+f"(c[0]), "+f"(c[1]), "+f"(c[2]), "+f"(c[3])
        : "r"(a[0]), "r"(a[1]), "r"(a[2]), "r"(a[3]), "r"(b[0]), "r"(b[1]));
}
// hi = rn_f16(v), lo = rn_f16(v - float(hi)) for a pair (vx, vy); packed f16x2.
__device__ __forceinline__ void split_pack(float vx, float vy,
                                           uint32_t& hp, uint32_t& lp) {
    asm("cvt.rn.f16x2.f32 %0, %1, %2;" : "=r"(hp) : "f"(vy), "f"(vx));
    __half2 h2 = *reinterpret_cast<__half2*>(&hp);
    float2 hf = __half22float2(h2);
    float rx = vx - hf.x;
    float ry = vy - hf.y;
    asm("cvt.rn.f16x2.f32 %0, %1, %2;" : "=r"(lp) : "f"(ry), "f"(rx));
}
__device__ __forceinline__ void split_pack_s(float vx, float vy,
                                             uint32_t& hp, uint32_t& lp) {
    __half hx = __float2half_rn(vx);
    __half hy = __float2half_rn(vy);
    __half lx = __float2half_rn(vx - __half2float(hx));
    __half ly = __float2half_rn(vy - __half2float(hy));
    hp = (uint32_t)__half_as_ushort(hx)
       | ((uint32_t)__half_as_ushort(hy) << 16);
    lp = (uint32_t)__half_as_ushort(lx)
       | ((uint32_t)__half_as_ushort(ly) << 16);
}
__device__ __forceinline__ void cp_async16(uint32_t dst, const void* src,
                                           int srcsize) {
    asm volatile("cp.async.cg.shared.global [%0], [%1], 16, %2;"
                 :: "r"(dst), "l"(src), "r"(srcsize) : "memory");
}
#define CP_COMMIT() asm volatile("cp.async.commit_group;" ::: "memory")
#define CP_WAIT0()  asm volatile("cp.async.wait_group 0;" ::: "memory")

// ---------------------------------------------------------------------------
// NCHW -> NHWC transpose of x, fused with fp16 hi/lo split
// ---------------------------------------------------------------------------
__global__ void transpose_x_kernel(const float* __restrict__ x) {
    __shared__ float tile[32][33];
    int b = blockIdx.z;
    int hw0 = blockIdx.x * 32;
    int c0 = blockIdx.y * 32;
    const float* xb = x + (size_t)b * C_IN * HW;
    #pragma unroll
    for (int i = threadIdx.y; i < 32; i += 8)
        tile[i][threadIdx.x] = xb[(size_t)(c0 + i) * HW + hw0 + threadIdx.x];
    __syncthreads();
    size_t base = (size_t)b * HW * C_IN;
    #pragma unroll
    for (int i = threadIdx.y; i < 32; i += 8) {
        float v = tile[threadIdx.x][i];
        size_t idx = base + (size_t)(hw0 + i) * C_IN + c0 + threadIdx.x;
        g_xt[idx] = v;
        __half hi = __float2half_rn(v);
        g_xbh[idx] = hi;
        g_xbl[idx] = __float2half_rn(v - __half2float(hi));
    }
}

// ---------------------------------------------------------------------------
// Weight prep: w_conv -> mma B-fragment order, single fp16 per weight
// ---------------------------------------------------------------------------
__global__ void prep_wfrag_kernel(const float* __restrict__ wc) {
    int i = blockIdx.x * 256 + threadIdx.x;   // 0 .. 9*8*8*32-1
    if (i >= K2 * 8 * 8 * 32) return;
    int lane = i & 31;
    int kc = (i >> 5) & 7;
    int g = (i >> 8) & 7;
    int t = i >> 11;
    int ob = g * 16 + (lane >> 2);
    int kb = kc * 16 + (lane & 3) * 2;
    #pragma unroll
    for (int m = 0; m < 4; m++) {
        int o = ob + ((m >> 1) << 3);
        int k = kb + ((m & 1) << 3);
        float v0 = wc[(o * 128 + k) * 9 + t];
        float v1 = wc[(o * 128 + k + 1) * 9 + t];
        uint32_t hp = (uint32_t)__half_as_ushort(__float2half_rn(v0))
                    | ((uint32_t)__half_as_ushort(__float2half_rn(v1)) << 16);
        g_wfh[i * 4 + m] = hp;
    }
}

// ---------------------------------------------------------------------------
// Weight prep: w_offset -> mma B-fragment order, fp16 hi/lo (3-term)
// ---------------------------------------------------------------------------
__global__ void prep_wofrag_kernel(const float* __restrict__ wo) {
    int i = blockIdx.x * 256 + threadIdx.x;   // 0 .. 9*2*8*32-1
    if (i >= K2 * 2 * 8 * 32) return;
    int lane = i & 31;
    int kc8 = (i >> 5) & 7;
    int ng = (i >> 8) & 1;
    int t = i >> 9;
    #pragma unroll
    for (int m = 0; m < 4; m++) {
        int o = ng * 16 + (lane >> 2) + ((m >> 1) << 3);
        int k = kc8 * 16 + (lane & 3) * 2 + ((m & 1) << 3);
        float v0 = (o < 18) ? wo[(o * 128 + k) * 9 + t] : 0.f;
        float v1 = (o < 18) ? wo[(o * 128 + k + 1) * 9 + t] : 0.f;
        uint32_t hp, lp;
        split_pack_s(v0, v1, hp, lp);
        g_wofh[i * 4 + m] = hp;
        g_wofl[i * 4 + m] = lp;
    }
}

// ---------------------------------------------------------------------------
// FUSED kernel (R14 structure, fp16).
//   Phase 1: offset conv (cp.async im2col pipeline, fp16 3-term) -> offbuf.
//   Phase 2: deformable conv, half-K double-buffered pipeline; float4
//            gather; A fp16 hi/lo split, W single fp16 -> 2 MMA terms.
// SMEM (83232 B): A0[0,32K) A1[32K,64K) cw[64K,+4K) coff[68K,+4K)
//                 offbuf[72K, +9504)
// ---------------------------------------------------------------------------
#define DSM_A0 0u
#define DSM_A1 32768u
#define DSM_CW 65536u
#define DSM_CO 69632u
#define DSM_OFF 73728u
#define DSMEM_BYTES 83232

__global__ __launch_bounds__(256, 2) void fused_mma(float* __restrict__ out) {
    extern __shared__ char smem[];
    const uint32_t sb = smem_u32(smem);
    const int tid = threadIdx.x;
    const int lane = tid & 31;
    const int wid = tid >> 5;
    const int b = blockIdx.x >> 5;
    const int pix0 = (blockIdx.x & 31) * 128;

    float* offbuf = (float*)(smem + DSM_OFF);   // [ch][132]

    // ======================= Phase 1: offset conv =======================
    {
        float acc[4][4] = {};

        auto stage = [&](int hh) {
            int tap = hh >> 1;
            int c0 = (hh & 1) * 64;
            int ky = tap / 3 - 1, kx = tap % 3 - 1;
            uint32_t ab = sb + ((hh & 1) ? DSM_A1 : DSM_A0);
            #pragma unroll
            for (int q = 0; q < 8; q++) {
                int cid = tid + 256 * q;
                int p = cid >> 4, sub = cid & 15;
                int cc = sub & 7;
                int gp = pix0 + p;
                int y = (gp >> 6) + ky;
                int xx = (gp & 63) + kx;
                bool ok = ((unsigned)y < 64u) && ((unsigned)xx < 64u);
                const __half* sp = (sub < 8 ? g_xbh : g_xbl)
                    + ((size_t)b * HW + (ok ? ((y << 6) + xx) : 0)) * 128
                    + c0 + cc * 8;
                uint32_t dst = ab + (uint32_t)p * 256u
                             + ((uint32_t)(cc ^ (p & 7)) << 4)
                             + (sub < 8 ? 0u : 128u);
                cp_async16(dst, sp, ok ? 16 : 0);
            }
        };

        stage(0);
        CP_COMMIT();

        for (int hh = 0; hh < 18; hh++) {
            CP_WAIT0();
            __syncthreads();
            if (hh + 1 < 18) { stage(hh + 1); CP_COMMIT(); }

            int tap = hh >> 1, half = hh & 1;
            uint32_t abu = sb + (half ? DSM_A1 : DSM_A0);
            #pragma unroll
            for (int kc = 0; kc < 4; kc++) {
                uint32_t ah[4], al[4];
                int mat = lane >> 3;
                int arow = wid * 16 + (lane & 7) + ((mat & 1) << 3);
                int kcol = kc * 16 + ((mat >> 1) << 3);
                uint32_t c = (uint32_t)(kcol >> 3);
                uint32_t aoff = (uint32_t)arow * 256u
                              + ((c ^ ((uint32_t)arow & 7u)) << 4);
                ldsm_x4(ah, abu + aoff);
                ldsm_x4(al, abu + aoff + 128);
                #pragma unroll
                for (int ng = 0; ng < 2; ng++) {
                    size_t fi = ((((size_t)tap * 2 + ng) * 8 + half * 4 + kc)
                                 * 32 + lane) * 4;
                    uint4 whf = *(const uint4*)(g_wofh + fi);
                    uint4 wlf = *(const uint4*)(g_wofl + fi);
                    uint32_t bh[4] = {whf.x, whf.y, whf.z, whf.w};
                    uint32_t bl[4] = {wlf.x, wlf.y, wlf.z, wlf.w};
                    mma_f16(acc[ng * 2 + 0], ah, bh + 0);
                    mma_f16(acc[ng * 2 + 1], ah, bh + 2);
                    mma_f16(acc[ng * 2 + 0], al, bh + 0);
                    mma_f16(acc[ng * 2 + 1], al, bh + 2);
                    mma_f16(acc[ng * 2 + 0], ah, bl + 0);
                    mma_f16(acc[ng * 2 + 1], ah, bl + 2);
                }
            }
        }
        __syncthreads();   // phase-1 MMAs done before offbuf writes race reads

        int pl = wid * 16 + (lane >> 2);
        #pragma unroll
        for (int nt = 0; nt < 4; nt++) {
            int ch = nt * 8 + (lane & 3) * 2;
            if (ch < 18) {
                offbuf[ch * 132 + pl]            = acc[nt][0];
                offbuf[(ch + 1) * 132 + pl]      = acc[nt][1];
                offbuf[ch * 132 + pl + 8]        = acc[nt][2];
                offbuf[(ch + 1) * 132 + pl + 8]  = acc[nt][3];
            }
        }
        __syncthreads();
    }

    // ======================= Phase 2: deformable conv ====================
    const int wy = wid & 3;          // px group: 32 px
    const int wx = wid >> 2;         // out group: 64 o

    float* cwbuf = (float*)(smem + DSM_CW);   // [par][j*128+p]
    int* cobuf = (int*)(smem + DSM_CO);
    const float* xb = g_xt + (size_t)b * HW * C_IN;

    float acc[2][8][4] = {};

    // per-tap bilinear setup (128 threads, 1 px / 4 corners each)
    auto tap_setup = [&](int tap) {
        if (tid < 128) {
            int p = tid;
            int par = tap & 1;
            int gp = pix0 + p;
            int h = gp >> 6, w = gp & 63;
            float dy = offbuf[(2 * tap) * 132 + p];
            float dx = offbuf[(2 * tap + 1) * 132 + p];
            float py = (float)(h - 1 + tap / 3) + dy;
            float px = (float)(w - 1 + tap % 3) + dx;
            float y0f = floorf(py), x0f = floorf(px);
            float fy = py - y0f, fx = px - x0f;
            #pragma unroll
            for (int j = 0; j < 4; j++) {
                float yf = y0f + (float)(j >> 1);
                float xf = x0f + (float)(j & 1);
                bool ok = (yf >= 0.f && yf < 64.f && xf >= 0.f && xf < 64.f);
                float wy_ = (j >> 1) ? fy : 1.f - fy;
                float wx_ = (j & 1) ? fx : 1.f - fx;
                cwbuf[par * 512 + j * 128 + p] = ok ? wy_ * wx_ : 0.f;
                int yi = (int)fminf(fmaxf(yf, 0.f), 63.f);
                int xi = (int)fminf(fmaxf(xf, 0.f), 63.f);
                cobuf[par * 512 + j * 128 + p] = ((yi << 6) + xi) << 7;
            }
        }
    };

    // float4 gather: warp covers 2 px/iter (16 lanes x 4 cin each), 8 iters.
    auto gather_half = [&](int hh2) {
        int par = (hh2 >> 1) & 1;
        int c0 = (hh2 & 1) * 64;
        char* ab = smem + ((hh2 & 1) ? DSM_A1 : DSM_A0);
        const float* cw = cwbuf + par * 512;
        const int* co = cobuf + par * 512;
        int ln = lane & 15;
        int side = lane >> 4;
        const float* base = xb + c0 + 4 * ln;
        #pragma unroll 4
        for (int i = 0; i < 8; i++) {
            int p = wid * 16 + i * 2 + side;
            float w0 = cw[p], w1 = cw[128 + p];
            float w2 = cw[256 + p], w3 = cw[384 + p];
            int o0 = co[p], o1 = co[128 + p];
            int o2 = co[256 + p], o3 = co[384 + p];
            float v0 = 0.f, v1 = 0.f, v2 = 0.f, v3 = 0.f;
            if (w0 != 0.f) { float4 t = *(const float4*)(base + o0);
                v0 += w0 * t.x; v1 += w0 * t.y; v2 += w0 * t.z; v3 += w0 * t.w; }
            if (w1 != 0.f) { float4 t = *(const float4*)(base + o1);
                v0 += w1 * t.x; v1 += w1 * t.y; v2 += w1 * t.z; v3 += w1 * t.w; }
            if (w2 != 0.f) { float4 t = *(const float4*)(base + o2);
                v0 += w2 * t.x; v1 += w2 * t.y; v2 += w2 * t.z; v3 += w2 * t.w; }
            if (w3 != 0.f) { float4 t = *(const float4*)(base + o3);
                v0 += w3 * t.x; v1 += w3 * t.y; v2 += w3 * t.z; v3 += w3 * t.w; }
            uint32_t hp0, lp0, hp1, lp1;
            split_pack(v0, v1, hp0, lp0);
            split_pack(v2, v3, hp1, lp1);
            uint32_t chunk = (uint32_t)(ln >> 1);
            uint32_t sw = (uint32_t)p * 256u
                        + ((chunk ^ ((uint32_t)p & 7u)) << 4)
                        + ((uint32_t)(ln & 1) << 3);
            *(uint2*)(ab + sw) = make_uint2(hp0, hp1);
            *(uint2*)(ab + sw + 128) = make_uint2(lp0, lp1);
        }
    };

    tap_setup(0);
    __syncthreads();
    gather_half(0);
    __syncthreads();

    for (int hh = 0; hh < 18; hh++) {
        int tap = hh >> 1;
        int half = hh & 1;

        if (half == 0 && tap + 1 < 9) tap_setup(tap + 1);
        if (hh + 1 < 18) gather_half(hh + 1);

        uint32_t abu = sb + (half ? DSM_A1 : DSM_A0);
        #pragma unroll
        for (int kc = 0; kc < 4; kc++) {
            uint32_t ah[2][4], al[2][4];
            #pragma unroll
            for (int mt = 0; mt < 2; mt++) {
                int mat = lane >> 3;
                int arow = wy * 32 + mt * 16 + (lane & 7) + ((mat & 1) << 3);
                int kcol = kc * 16 + ((mat >> 1) << 3);
                uint32_t c = (uint32_t)(kcol >> 3);
                uint32_t aoff = (uint32_t)arow * 256u
                              + ((c ^ ((uint32_t)arow & 7u)) << 4);
                ldsm_x4(ah[mt], abu + aoff);
                ldsm_x4(al[mt], abu + aoff + 128);
            }
            #pragma unroll
            for (int ng = 0; ng < 4; ng++) {
                int g = wx * 4 + ng;
                size_t fi = ((((size_t)tap * 8 + g) * 8 + half * 4 + kc) * 32
                             + lane) * 4;
                uint4 whf = *(const uint4*)(g_wfh + fi);
                uint32_t bh[4] = {whf.x, whf.y, whf.z, whf.w};
                #pragma unroll
                for (int mt = 0; mt < 2; mt++) {
                    mma_f16(acc[mt][ng * 2 + 0], ah[mt], bh + 0);
                    mma_f16(acc[mt][ng * 2 + 1], ah[mt], bh + 2);
                    mma_f16(acc[mt][ng * 2 + 0], al[mt], bh + 0);
                    mma_f16(acc[mt][ng * 2 + 1], al[mt], bh + 2);
                }
            }
        }
        __syncthreads();
    }

    // --- epilogue: c-frag -> out[b][o][px] ---
    float* ob = out + (size_t)b * 128 * HW;
    #pragma unroll
    for (int mt = 0; mt < 2; mt++) {
        int px0 = pix0 + wy * 32 + mt * 16 + (lane >> 2);
        #pragma unroll
        for (int nt = 0; nt < 8; nt++) {
            int o = wx * 64 + nt * 8 + (lane & 3) * 2;
            ob[(size_t)o * HW + px0]            = acc[mt][nt][0];
            ob[(size_t)(o + 1) * HW + px0]      = acc[mt][nt][1];
            ob[(size_t)o * HW + px0 + 8]        = acc[mt][nt][2];
            ob[(size_t)(o + 1) * HW + px0 + 8]  = acc[mt][nt][3];
        }
    }
}

// ---------------------------------------------------------------------------
extern "C" void kernel_launch(void* const* d_in, const int* in_sizes, int n_in,
                              void* d_out, int out_size) {
    const float* x  = (const float*)d_in[0];
    const float* wo = (const float*)d_in[1];   // w_offset
    const float* wc = (const float*)d_in[2];   // w_conv
    float* out = (float*)d_out;

    static bool attr_set = false;
    if (!attr_set) {
        cudaFuncSetAttribute(fused_mma,
                             cudaFuncAttributeMaxDynamicSharedMemorySize,
                             DSMEM_BYTES);
        attr_set = true;
    }

    dim3 tpb(32, 8);
    transpose_x_kernel<<<dim3(HW / 32, C_IN / 32, Bn), tpb>>>(x);
    prep_wfrag_kernel<<<(K2 * 8 * 8 * 32 + 255) / 256, 256>>>(wc);
    prep_wofrag_kernel<<<(K2 * 2 * 8 * 32 + 255) / 256, 256>>>(wo);
    fused_mma<<<Bn * (HW / 128), 256, DSMEM_BYTES>>>(out);
}

// round 16
// speedup vs baseline: 1.6791x; 1.1525x over previous
#include <cuda_runtime.h>
#include <cuda_fp16.h>
#include <cstdint>

#define Bn 8
#define C_IN 128
#define C_OUT 128
#define K2 9
#define HH 64
#define WW 64
#define HW 4096
#define NOFF 18

// Scratch (no cudaMalloc allowed)
__device__ float g_xt[Bn * HW * C_IN];            // x NHWC fp32: [b][y][x][c]
__device__ __half g_xbh[Bn * HW * C_IN];          // x NHWC fp16 hi
__device__ __half g_xbl[Bn * HW * C_IN];          // x NHWC fp16 lo
// w_conv in mma B-fragment order: [tap][o16-group(8)][k16(8)][lane(32)][mat(4)]
// single fp16 per weight (11-bit mantissa, rel err ~2^-12)
__device__ uint32_t g_wfh[K2 * 8 * 8 * 32 * 4];
// w_offset frags (fp16 hi/lo, 3-term): [tap][ng(2)][k16(8)][lane(32)][mat(4)]
__device__ uint32_t g_wofh[K2 * 2 * 8 * 32 * 4];
__device__ uint32_t g_wofl[K2 * 2 * 8 * 32 * 4];

// ---------------------------------------------------------------------------
// Helpers (portable PTX: ldmatrix + mma.sync + cp.async, sm_80+)
// ---------------------------------------------------------------------------
__device__ __forceinline__ uint32_t smem_u32(const void* p) {
    uint32_t a;
    asm("{ .reg .u64 t; cvta.to.shared.u64 t, %1; cvt.u32.u64 %0, t; }"
        : "=r"(a) : "l"(p));
    return a;
}
__device__ __forceinline__ void ldsm_x4(uint32_t* r, uint32_t addr) {
    asm volatile("ldmatrix.sync.aligned.m8n8.x4.shared.b16 {%0,%1,%2,%3}, [%4];"
                 : "=r"(r[0]), "=r"(r[1]), "=r"(r[2]), "=r"(r[3]) : "r"(addr));
}
__device__ __forceinline__ void mma_f16(float* c, const uint32_t* a,
                                        const uint32_t* b) {
    asm volatile(
        "mma.sync.aligned.m16n8k16.row.col.f32.f16.f16.f32 "
        "{%0,%1,%2,%3}, {%4,%5,%6,%7}, {%8,%9}, {%0,%1,%2,%3};"
        : "+f"(c[0]), "+f"(c[1]), "+f"(c[2]), "+f"(c[3])
        : "r"(a[0]), "r"(a[1]), "r"(a[2]), "r"(a[3]), "r"(b[0]), "r"(b[1]));
}
// single-precision -> packed fp16x2 (round-to-nearest)
__device__ __forceinline__ uint32_t pack_f16(float vx, float vy) {
    uint32_t hp;
    asm("cvt.rn.f16x2.f32 %0, %1, %2;" : "=r"(hp) : "f"(vy), "f"(vx));
    return hp;
}
__device__ __forceinline__ void split_pack_s(float vx, float vy,
                                             uint32_t& hp, uint32_t& lp) {
    __half hx = __float2half_rn(vx);
    __half hy = __float2half_rn(vy);
    __half lx = __float2half_rn(vx - __half2float(hx));
    __half ly = __float2half_rn(vy - __half2float(hy));
    hp = (uint32_t)__half_as_ushort(hx)
       | ((uint32_t)__half_as_ushort(hy) << 16);
    lp = (uint32_t)__half_as_ushort(lx)
       | ((uint32_t)__half_as_ushort(ly) << 16);
}
__device__ __forceinline__ void cp_async16(uint32_t dst, const void* src,
                                           int srcsize) {
    asm volatile("cp.async.cg.shared.global [%0], [%1], 16, %2;"
                 :: "r"(dst), "l"(src), "r"(srcsize) : "memory");
}
#define CP_COMMIT() asm volatile("cp.async.commit_group;" ::: "memory")
#define CP_WAIT0()  asm volatile("cp.async.wait_group 0;" ::: "memory")

// ---------------------------------------------------------------------------
// NCHW -> NHWC transpose of x, fused with fp16 hi/lo split
// ---------------------------------------------------------------------------
__global__ void transpose_x_kernel(const float* __restrict__ x) {
    __shared__ float tile[32][33];
    int b = blockIdx.z;
    int hw0 = blockIdx.x * 32;
    int c0 = blockIdx.y * 32;
    const float* xb = x + (size_t)b * C_IN * HW;
    #pragma unroll
    for (int i = threadIdx.y; i < 32; i += 8)
        tile[i][threadIdx.x] = xb[(size_t)(c0 + i) * HW + hw0 + threadIdx.x];
    __syncthreads();
    size_t base = (size_t)b * HW * C_IN;
    #pragma unroll
    for (int i = threadIdx.y; i < 32; i += 8) {
        float v = tile[threadIdx.x][i];
        size_t idx = base + (size_t)(hw0 + i) * C_IN + c0 + threadIdx.x;
        g_xt[idx] = v;
        __half hi = __float2half_rn(v);
        g_xbh[idx] = hi;
        g_xbl[idx] = __float2half_rn(v - __half2float(hi));
    }
}

// ---------------------------------------------------------------------------
// Weight prep: w_conv -> mma B-fragment order, single fp16 per weight
// ---------------------------------------------------------------------------
__global__ void prep_wfrag_kernel(const float* __restrict__ wc) {
    int i = blockIdx.x * 256 + threadIdx.x;   // 0 .. 9*8*8*32-1
    if (i >= K2 * 8 * 8 * 32) return;
    int lane = i & 31;
    int kc = (i >> 5) & 7;
    int g = (i >> 8) & 7;
    int t = i >> 11;
    int ob = g * 16 + (lane >> 2);
    int kb = kc * 16 + (lane & 3) * 2;
    #pragma unroll
    for (int m = 0; m < 4; m++) {
        int o = ob + ((m >> 1) << 3);
        int k = kb + ((m & 1) << 3);
        float v0 = wc[(o * 128 + k) * 9 + t];
        float v1 = wc[(o * 128 + k + 1) * 9 + t];
        uint32_t hp = (uint32_t)__half_as_ushort(__float2half_rn(v0))
                    | ((uint32_t)__half_as_ushort(__float2half_rn(v1)) << 16);
        g_wfh[i * 4 + m] = hp;
    }
}

// ---------------------------------------------------------------------------
// Weight prep: w_offset -> mma B-fragment order, fp16 hi/lo (3-term)
// ---------------------------------------------------------------------------
__global__ void prep_wofrag_kernel(const float* __restrict__ wo) {
    int i = blockIdx.x * 256 + threadIdx.x;   // 0 .. 9*2*8*32-1
    if (i >= K2 * 2 * 8 * 32) return;
    int lane = i & 31;
    int kc8 = (i >> 5) & 7;
    int ng = (i >> 8) & 1;
    int t = i >> 9;
    #pragma unroll
    for (int m = 0; m < 4; m++) {
        int o = ng * 16 + (lane >> 2) + ((m >> 1) << 3);
        int k = kc8 * 16 + (lane & 3) * 2 + ((m & 1) << 3);
        float v0 = (o < 18) ? wo[(o * 128 + k) * 9 + t] : 0.f;
        float v1 = (o < 18) ? wo[(o * 128 + k + 1) * 9 + t] : 0.f;
        uint32_t hp, lp;
        split_pack_s(v0, v1, hp, lp);
        g_wofh[i * 4 + m] = hp;
        g_wofl[i * 4 + m] = lp;
    }
}

// ---------------------------------------------------------------------------
// FUSED kernel.
//   Phase 1: offset conv (cp.async im2col pipeline, fp16 3-term) -> offbuf.
//     Offsets NEED the 3-term split: offset error amplifies ~25x into the
//     output (sigma~34 offsets, ~0.7/px sensitivity).
//   Phase 2: deformable conv, half-K double-buffered pipeline; float4
//     gather; SINGLE fp16 A x single fp16 W -> 1 MMA term.
//     A half-row = 128B (64 cin fp16), 16B chunks XOR-swizzled by (p&7).
// SMEM (83232 B): A0[0,32K) A1[32K,64K) cw[64K,+4K) coff[68K,+4K)
//                 offbuf[72K, +9504)   (phase 2 uses 16KB of each A buffer)
// ---------------------------------------------------------------------------
#define DSM_A0 0u
#define DSM_A1 32768u
#define DSM_CW 65536u
#define DSM_CO 69632u
#define DSM_OFF 73728u
#define DSMEM_BYTES 83232

__global__ __launch_bounds__(256, 2) void fused_mma(float* __restrict__ out) {
    extern __shared__ char smem[];
    const uint32_t sb = smem_u32(smem);
    const int tid = threadIdx.x;
    const int lane = tid & 31;
    const int wid = tid >> 5;
    const int b = blockIdx.x >> 5;
    const int pix0 = (blockIdx.x & 31) * 128;

    float* offbuf = (float*)(smem + DSM_OFF);   // [ch][132]

    // ======================= Phase 1: offset conv =======================
    {
        float acc[4][4] = {};

        auto stage = [&](int hh) {
            int tap = hh >> 1;
            int c0 = (hh & 1) * 64;
            int ky = tap / 3 - 1, kx = tap % 3 - 1;
            uint32_t ab = sb + ((hh & 1) ? DSM_A1 : DSM_A0);
            #pragma unroll
            for (int q = 0; q < 8; q++) {
                int cid = tid + 256 * q;
                int p = cid >> 4, sub = cid & 15;
                int cc = sub & 7;
                int gp = pix0 + p;
                int y = (gp >> 6) + ky;
                int xx = (gp & 63) + kx;
                bool ok = ((unsigned)y < 64u) && ((unsigned)xx < 64u);
                const __half* sp = (sub < 8 ? g_xbh : g_xbl)
                    + ((size_t)b * HW + (ok ? ((y << 6) + xx) : 0)) * 128
                    + c0 + cc * 8;
                uint32_t dst = ab + (uint32_t)p * 256u
                             + ((uint32_t)(cc ^ (p & 7)) << 4)
                             + (sub < 8 ? 0u : 128u);
                cp_async16(dst, sp, ok ? 16 : 0);
            }
        };

        stage(0);
        CP_COMMIT();

        for (int hh = 0; hh < 18; hh++) {
            CP_WAIT0();
            __syncthreads();
            if (hh + 1 < 18) { stage(hh + 1); CP_COMMIT(); }

            int tap = hh >> 1, half = hh & 1;
            uint32_t abu = sb + (half ? DSM_A1 : DSM_A0);
            #pragma unroll
            for (int kc = 0; kc < 4; kc++) {
                uint32_t ah[4], al[4];
                int mat = lane >> 3;
                int arow = wid * 16 + (lane & 7) + ((mat & 1) << 3);
                int kcol = kc * 16 + ((mat >> 1) << 3);
                uint32_t c = (uint32_t)(kcol >> 3);
                uint32_t aoff = (uint32_t)arow * 256u
                              + ((c ^ ((uint32_t)arow & 7u)) << 4);
                ldsm_x4(ah, abu + aoff);
                ldsm_x4(al, abu + aoff + 128);
                #pragma unroll
                for (int ng = 0; ng < 2; ng++) {
                    size_t fi = ((((size_t)tap * 2 + ng) * 8 + half * 4 + kc)
                                 * 32 + lane) * 4;
                    uint4 whf = *(const uint4*)(g_wofh + fi);
                    uint4 wlf = *(const uint4*)(g_wofl + fi);
                    uint32_t bh[4] = {whf.x, whf.y, whf.z, whf.w};
                    uint32_t bl[4] = {wlf.x, wlf.y, wlf.z, wlf.w};
                    mma_f16(acc[ng * 2 + 0], ah, bh + 0);
                    mma_f16(acc[ng * 2 + 1], ah, bh + 2);
                    mma_f16(acc[ng * 2 + 0], al, bh + 0);
                    mma_f16(acc[ng * 2 + 1], al, bh + 2);
                    mma_f16(acc[ng * 2 + 0], ah, bl + 0);
                    mma_f16(acc[ng * 2 + 1], ah, bl + 2);
                }
            }
        }
        __syncthreads();   // phase-1 MMAs done before offbuf writes race reads

        int pl = wid * 16 + (lane >> 2);
        #pragma unroll
        for (int nt = 0; nt < 4; nt++) {
            int ch = nt * 8 + (lane & 3) * 2;
            if (ch < 18) {
                offbuf[ch * 132 + pl]            = acc[nt][0];
                offbuf[(ch + 1) * 132 + pl]      = acc[nt][1];
                offbuf[ch * 132 + pl + 8]        = acc[nt][2];
                offbuf[(ch + 1) * 132 + pl + 8]  = acc[nt][3];
            }
        }
        __syncthreads();
    }

    // ======================= Phase 2: deformable conv ====================
    const int wy = wid & 3;          // px group: 32 px
    const int wx = wid >> 2;         // out group: 64 o

    float* cwbuf = (float*)(smem + DSM_CW);   // [par][j*128+p]
    int* cobuf = (int*)(smem + DSM_CO);
    const float* xb = g_xt + (size_t)b * HW * C_IN;

    float acc[2][8][4] = {};

    // per-tap bilinear setup (128 threads, 1 px / 4 corners each)
    auto tap_setup = [&](int tap) {
        if (tid < 128) {
            int p = tid;
            int par = tap & 1;
            int gp = pix0 + p;
            int h = gp >> 6, w = gp & 63;
            float dy = offbuf[(2 * tap) * 132 + p];
            float dx = offbuf[(2 * tap + 1) * 132 + p];
            float py = (float)(h - 1 + tap / 3) + dy;
            float px = (float)(w - 1 + tap % 3) + dx;
            float y0f = floorf(py), x0f = floorf(px);
            float fy = py - y0f, fx = px - x0f;
            #pragma unroll
            for (int j = 0; j < 4; j++) {
                float yf = y0f + (float)(j >> 1);
                float xf = x0f + (float)(j & 1);
                bool ok = (yf >= 0.f && yf < 64.f && xf >= 0.f && xf < 64.f);
                float wy_ = (j >> 1) ? fy : 1.f - fy;
                float wx_ = (j & 1) ? fx : 1.f - fx;
                cwbuf[par * 512 + j * 128 + p] = ok ? wy_ * wx_ : 0.f;
                int yi = (int)fminf(fmaxf(yf, 0.f), 63.f);
                int xi = (int)fminf(fmaxf(xf, 0.f), 63.f);
                cobuf[par * 512 + j * 128 + p] = ((yi << 6) + xi) << 7;
            }
        }
    };

    // float4 gather, single-fp16 output: warp = 2 px/iter, 8 iters per half.
    // A half-row: 128B = 64 cin fp16, 16B chunks swizzled by (p&7).
    auto gather_half = [&](int hh2) {
        int par = (hh2 >> 1) & 1;
        int c0 = (hh2 & 1) * 64;
        char* ab = smem + ((hh2 & 1) ? DSM_A1 : DSM_A0);
        const float* cw = cwbuf + par * 512;
        const int* co = cobuf + par * 512;
        int ln = lane & 15;
        int side = lane >> 4;
        const float* base = xb + c0 + 4 * ln;
        #pragma unroll 4
        for (int i = 0; i < 8; i++) {
            int p = wid * 16 + i * 2 + side;
            float w0 = cw[p], w1 = cw[128 + p];
            float w2 = cw[256 + p], w3 = cw[384 + p];
            int o0 = co[p], o1 = co[128 + p];
            int o2 = co[256 + p], o3 = co[384 + p];
            float v0 = 0.f, v1 = 0.f, v2 = 0.f, v3 = 0.f;
            if (w0 != 0.f) { float4 t = *(const float4*)(base + o0);
                v0 += w0 * t.x; v1 += w0 * t.y; v2 += w0 * t.z; v3 += w0 * t.w; }
            if (w1 != 0.f) { float4 t = *(const float4*)(base + o1);
                v0 += w1 * t.x; v1 += w1 * t.y; v2 += w1 * t.z; v3 += w1 * t.w; }
            if (w2 != 0.f) { float4 t = *(const float4*)(base + o2);
                v0 += w2 * t.x; v1 += w2 * t.y; v2 += w2 * t.z; v3 += w2 * t.w; }
            if (w3 != 0.f) { float4 t = *(const float4*)(base + o3);
                v0 += w3 * t.x; v1 += w3 * t.y; v2 += w3 * t.z; v3 += w3 * t.w; }
            uint32_t hp0 = pack_f16(v0, v1);
            uint32_t hp1 = pack_f16(v2, v3);
            uint32_t chunk = (uint32_t)(ln >> 1);
            uint32_t sw = (uint32_t)p * 128u
                        + ((chunk ^ ((uint32_t)p & 7u)) << 4)
                        + ((uint32_t)(ln & 1) << 3);
            *(uint2*)(ab + sw) = make_uint2(hp0, hp1);
        }
    };

    tap_setup(0);
    __syncthreads();
    gather_half(0);
    __syncthreads();

    for (int hh = 0; hh < 18; hh++) {
        int tap = hh >> 1;
        int half = hh & 1;

        if (half == 0 && tap + 1 < 9) tap_setup(tap + 1);
        if (hh + 1 < 18) gather_half(hh + 1);

        uint32_t abu = sb + (half ? DSM_A1 : DSM_A0);
        #pragma unroll
        for (int kc = 0; kc < 4; kc++) {
            uint32_t ah[2][4];
            #pragma unroll
            for (int mt = 0; mt < 2; mt++) {
                int mat = lane >> 3;
                int arow = wy * 32 + mt * 16 + (lane & 7) + ((mat & 1) << 3);
                int kcol = kc * 16 + ((mat >> 1) << 3);
                uint32_t c = (uint32_t)(kcol >> 3);
                uint32_t aoff = (uint32_t)arow * 128u
                              + ((c ^ ((uint32_t)arow & 7u)) << 4);
                ldsm_x4(ah[mt], abu + aoff);
            }
            #pragma unroll
            for (int ng = 0; ng < 4; ng++) {
                int g = wx * 4 + ng;
                size_t fi = ((((size_t)tap * 8 + g) * 8 + half * 4 + kc) * 32
                             + lane) * 4;
                uint4 whf = *(const uint4*)(g_wfh + fi);
                uint32_t bh[4] = {whf.x, whf.y, whf.z, whf.w};
                #pragma unroll
                for (int mt = 0; mt < 2; mt++) {
                    mma_f16(acc[mt][ng * 2 + 0], ah[mt], bh + 0);
                    mma_f16(acc[mt][ng * 2 + 1], ah[mt], bh + 2);
                }
            }
        }
        __syncthreads();
    }

    // --- epilogue: c-frag -> out[b][o][px] ---
    float* ob = out + (size_t)b * 128 * HW;
    #pragma unroll
    for (int mt = 0; mt < 2; mt++) {
        int px0 = pix0 + wy * 32 + mt * 16 + (lane >> 2);
        #pragma unroll
        for (int nt = 0; nt < 8; nt++) {
            int o = wx * 64 + nt * 8 + (lane & 3) * 2;
            ob[(size_t)o * HW + px0]            = acc[mt][nt][0];
            ob[(size_t)(o + 1) * HW + px0]      = acc[mt][nt][1];
            ob[(size_t)o * HW + px0 + 8]        = acc[mt][nt][2];
            ob[(size_t)(o + 1) * HW + px0 + 8]  = acc[mt][nt][3];
        }
    }
}

// ---------------------------------------------------------------------------
extern "C" void kernel_launch(void* const* d_in, const int* in_sizes, int n_in,
                              void* d_out, int out_size) {
    const float* x  = (const float*)d_in[0];
    const float* wo = (const float*)d_in[1];   // w_offset
    const float* wc = (const float*)d_in[2];   // w_conv
    float* out = (float*)d_out;

    static bool attr_set = false;
    if (!attr_set) {
        cudaFuncSetAttribute(fused_mma,
                             cudaFuncAttributeMaxDynamicSharedMemorySize,
                             DSMEM_BYTES);
        attr_set = true;
    }

    dim3 tpb(32, 8);
    transpose_x_kernel<<<dim3(HW / 32, C_IN / 32, Bn), tpb>>>(x);
    prep_wfrag_kernel<<<(K2 * 8 * 8 * 32 + 255) / 256, 256>>>(wc);
    prep_wofrag_kernel<<<(K2 * 2 * 8 * 32 + 255) / 256, 256>>>(wo);
    fused_mma<<<Bn * (HW / 128), 256, DSMEM_BYTES>>>(out);
}